// round 10
// baseline (speedup 1.0000x reference)
#include <cuda_runtime.h>

#define BB 16
#define SS 2048
#define KK 16
#define LL 64
#define II 256
#define NS (BB*SS)        // 32768
#define CH 16
#define NC (SS/CH)        // 128 chunks per batch
#define TOTCH (BB*NC)     // 2048 chunks total
#define SUPW 8
#define NSUP (NC/SUPW)    // 16 super-chunks per batch

#define SPB 16            // samples per emissions block == CH
#define TPB 256

#define FULL 0xffffffffu

// ---- packed f32x2 helpers ----
typedef unsigned long long u64t;
#define FMA2(d,a,b,c) asm volatile("fma.rn.f32x2 %0, %1, %2, %3;" : "=l"(d) : "l"(a), "l"(b), "l"(c))
#define ADD2(d,a,b)   asm volatile("add.rn.f32x2 %0, %1, %2;" : "=l"(d) : "l"(a), "l"(b))
#define MUL2(d,a,b)   asm volatile("mul.rn.f32x2 %0, %1, %2;" : "=l"(d) : "l"(a), "l"(b))
#define PK2(d,lo,hi)  asm volatile("mov.b64 %0, {%1, %2};" : "=l"(d) : "r"(lo), "r"(hi))
#define UPK2(lo,hi,s) asm volatile("mov.b64 {%0, %1}, %2;" : "=r"(lo), "=r"(hi) : "l"(s))
#define LDS2(a,b,addr) asm volatile("ld.shared.v2.u64 {%0, %1}, [%2];" : "=l"(a), "=l"(b) : "r"(addr))

__device__ __forceinline__ unsigned s2u(const void* p) {
    unsigned r;
    asm("{ .reg .u64 t; cvta.to.shared.u64 t, %1; cvt.u32.u64 %0, t; }" : "=r"(r) : "l"(p));
    return r;
}

// Scratch (device globals; no allocation allowed)
__device__ __align__(16) float g_emp[NS*KK];          // em - rowmax
__device__ __align__(16) float g_rowmax[NS];
__device__ float g_A[KK*KK];
__device__ __align__(16) float g_Rn[TOTCH][KK*KK];    // chunk matrix, row max = 1
__device__ __align__(16) float g_rowlog[TOTCH][KK];
__device__ __align__(16) float g_rmsum[TOTCH];
__device__ float g_qb[TOTCH][KK];
__device__ float g_Cb[TOTCH];

// smem layout (floats)
#define SM_ZA    0                   // z_a [64][16]
#define SM_ZB    (SM_ZA + 1024)      // z_b [16][68]
#define SM_D     (SM_ZB + 1088)      // d   [16][256]
#define SM_WS    (SM_D + 4096)       // ws  [16][260]
#define SM_IV    (SM_WS + 4160)      // invvar [16][64]
#define SM_NM    (SM_IV + 1024)      // -mu    [16][64]
#define SM_AS    (SM_NM + 1024)      // A   [16][16]
#define SM_ES    (SM_AS + 256)       // E   [16][16]
#define SM_RMX   (SM_ES + 256)       // rowmax [16]
#define SM_LVS   (SM_RMX + 16)       // lvsum [16]
#define SM_WS2   (SM_LVS + 16)       // ws2 [16]
#define SM_TOTAL (SM_WS2 + 16)

// ---------------------------------------------------------------------------
// Kernel A: setup-lite + emissions + per-chunk matrix product (fused phase1)
// ---------------------------------------------------------------------------
__global__ void __launch_bounds__(TPB) kernelA(
    const float* __restrict__ Y, const float* __restrict__ Z,
    const float* __restrict__ Wz, const float* __restrict__ Ws,
    const float* __restrict__ bdec, const float* __restrict__ lv,
    const float* __restrict__ mu, const float* __restrict__ trans)
{
    extern __shared__ __align__(16) float smA[];
    float* z_a  = smA + SM_ZA;
    float* z_b  = smA + SM_ZB;
    float* d_s  = smA + SM_D;
    float* ws_s = smA + SM_WS;
    float* iv_s = smA + SM_IV;
    float* nm_s = smA + SM_NM;
    float* A_s  = smA + SM_AS;
    float* E_s  = smA + SM_ES;
    float* rmx_s= smA + SM_RMX;
    float* lvs_s= smA + SM_LVS;
    float* ws2_s= smA + SM_WS2;

    int tid = threadIdx.x;
    int w = tid >> 5, lane = tid & 31;
    int bid = blockIdx.x;
    int s0 = bid * SPB;

    // ---- stage 0: per-block parameter prep ----
    #pragma unroll
    for (int e = 0; e < 4; e++) {
        int idx = tid + 256*e;
        float l = __ldg(lv + idx);
        iv_s[idx] = 1.0f / (expf(l) + 1e-8f);
        nm_s[idx] = -__ldg(mu + idx);
    }
    #pragma unroll
    for (int rr = 0; rr < 2; rr++) {
        int r = 2*w + rr;
        float sl = __ldg(lv + r*LL + lane) + __ldg(lv + r*LL + 32 + lane);
        #pragma unroll
        for (int off = 16; off; off >>= 1) sl += __shfl_xor_sync(FULL, sl, off);
        if (lane == 0) lvs_s[r] = sl;
        float s2 = 0.f;
        #pragma unroll
        for (int e = 0; e < 8; e++) {
            float v = __ldg(Ws + r*II + lane + 32*e);
            s2 = fmaf(v, v, s2);
        }
        #pragma unroll
        for (int off = 16; off; off >>= 1) s2 += __shfl_xor_sync(FULL, s2, off);
        if (lane == 0) ws2_s[r] = s2;
    }
    if (w == 0) {
        // row-softmax of trans into A_s
        #pragma unroll
        for (int j = 0; j < KK; j++) {
            float v = (lane < 16) ? __ldg(trans + j*KK + lane) : -1e30f;
            float mx = v;
            #pragma unroll
            for (int off = 8; off; off >>= 1) mx = fmaxf(mx, __shfl_xor_sync(FULL, mx, off));
            float ex = (lane < 16) ? expf(v - mx) : 0.f;
            float se = ex;
            #pragma unroll
            for (int off = 8; off; off >>= 1) se += __shfl_xor_sync(FULL, se, off);
            if (lane < 16) {
                float a = expf(v - mx - logf(se));
                A_s[j*KK + lane] = a;
                if (bid == 0) g_A[j*KK + lane] = a;
            }
        }
    }

    // ---- load z and Ws tiles ----
    #pragma unroll
    for (int e = 0; e < (SPB*LL)/TPB; e++) {
        int idx = tid + TPB*e;
        int s = idx >> 6, l = idx & 63;
        float v = Z[(s0 + s)*LL + l];
        z_a[l*SPB + s] = v;
        z_b[s*(LL+4) + l] = v;
    }
    #pragma unroll
    for (int e = 0; e < (KK*II)/TPB; e++) {
        int idx = tid + TPB*e;
        ws_s[(idx >> 8)*(II+4) + (idx & 255)] = Ws[idx];
    }
    __syncthreads();

    // ---- Phase A: base = b_dec + z @ Wz (packed over sample pairs) ----
    {
        u64t bp[8];
        float bd = __ldg(bdec + tid);
        u64t bdp; PK2(bdp, __float_as_uint(bd), __float_as_uint(bd));
        #pragma unroll
        for (int p = 0; p < 8; p++) bp[p] = bdp;

        unsigned za0 = s2u(z_a);
        #pragma unroll 4
        for (int l = 0; l < LL; l++) {
            float wz = __ldg(Wz + l*II + tid);
            u64t wzp; PK2(wzp, __float_as_uint(wz), __float_as_uint(wz));
            unsigned row = za0 + l*(SPB*4);
            u64t z0,z1,z2,z3,z4,z5,z6,z7;
            LDS2(z0, z1, row);
            LDS2(z2, z3, row + 16);
            LDS2(z4, z5, row + 32);
            LDS2(z6, z7, row + 48);
            FMA2(bp[0], z0, wzp, bp[0]);
            FMA2(bp[1], z1, wzp, bp[1]);
            FMA2(bp[2], z2, wzp, bp[2]);
            FMA2(bp[3], z3, wzp, bp[3]);
            FMA2(bp[4], z4, wzp, bp[4]);
            FMA2(bp[5], z5, wzp, bp[5]);
            FMA2(bp[6], z6, wzp, bp[6]);
            FMA2(bp[7], z7, wzp, bp[7]);
        }
        #pragma unroll
        for (int p = 0; p < 8; p++) {
            unsigned u0, u1; UPK2(u0, u1, bp[p]);
            int s = 2*p;
            float y0 = __ldg(Y + (s0 + s)*II + tid);
            float y1 = __ldg(Y + (s0 + s + 1)*II + tid);
            d_s[s*II + tid]       = y0 - __uint_as_float(u0);
            d_s[(s + 1)*II + tid] = y1 - __uint_as_float(u1);
        }
    }
    __syncthreads();

    // ---- Phase B: thread (sample si, state k) ----
    int si = tid >> 4;
    int k  = tid & 15;

    float sd = 0.f;
    #pragma unroll
    for (int t = 0; t < 16; t++) {
        float dv = d_s[si*II + t*16 + k];
        sd = fmaf(dv, dv, sd);
    }
    #pragma unroll
    for (int off = 8; off; off >>= 1) sd += __shfl_xor_sync(FULL, sd, off);

    float dot;
    {
        unsigned drow = s2u(&d_s[si*II]);
        unsigned wrow = s2u(&ws_s[k*(II+4)]);
        u64t a0 = 0ull, a1 = 0ull;
        #pragma unroll 8
        for (int i = 0; i < II/4; i++) {
            u64t d0, d1, w0, w1;
            LDS2(d0, d1, drow + i*16);
            LDS2(w0, w1, wrow + i*16);
            FMA2(a0, d0, w0, a0);
            FMA2(a1, d1, w1, a1);
        }
        unsigned l0, h0, l1, h1;
        UPK2(l0, h0, a0); UPK2(l1, h1, a1);
        dot = (__uint_as_float(l0) + __uint_as_float(h0))
            + (__uint_as_float(l1) + __uint_as_float(h1));
    }
    float accy = sd - 2.f*dot + ws2_s[k];

    float accz;
    {
        unsigned zrow = s2u(&z_b[si*(LL+4)]);
        unsigned nrow = s2u(&nm_s[k*LL]);
        unsigned irow = s2u(&iv_s[k*LL]);
        u64t a0 = 0ull, a1 = 0ull;
        #pragma unroll
        for (int i = 0; i < LL/4; i++) {
            u64t z0, z1, m0, m1, v0, v1;
            LDS2(z0, z1, zrow + i*16);
            LDS2(m0, m1, nrow + i*16);
            LDS2(v0, v1, irow + i*16);
            u64t t0, t1;
            ADD2(t0, z0, m0);
            ADD2(t1, z1, m1);
            MUL2(t0, t0, t0);
            MUL2(t1, t1, t1);
            FMA2(a0, t0, v0, a0);
            FMA2(a1, t1, v1, a1);
        }
        unsigned l0, h0, l1, h1;
        UPK2(l0, h0, a0); UPK2(l1, h1, a1);
        accz = (__uint_as_float(l0) + __uint_as_float(h0))
             + (__uint_as_float(l1) + __uint_as_float(h1));
    }

    const float LLOG2PI = 117.62413f;  // 64 * log(2*pi)
    float em = -0.5f*accy - 0.5f*(lvs_s[k] + accz + LLOG2PI);

    float m = em;
    #pragma unroll
    for (int off = 8; off; off >>= 1)
        m = fmaxf(m, __shfl_xor_sync(FULL, m, off));

    float emp = em - m;
    float E = __expf(fmaxf(emp, -80.f));

    g_emp[(size_t)s0*KK + tid] = emp;   // == sample*KK + k (coalesced)
    E_s[si*16 + k] = E;
    if (k == 0) {
        g_rowmax[s0 + si] = m;
        rmx_s[si] = m;
    }
    __syncthreads();

    // ---- fused phase1 tail: warp 0 builds the chunk matrix from smem ----
    if (w != 0) return;

    int cl = bid % NC;
    int us = (cl == 0) ? 1 : 0;
    int iRow = lane >> 1, h = lane & 1;

    float R[8];
    #pragma unroll
    for (int kk2 = 0; kk2 < 8; kk2++)
        R[kk2] = (iRow == h*8 + kk2) ? 1.f : 0.f;

    float rowlog = 0.f, rmsum = 0.f;

    #pragma unroll
    for (int u = 0; u < CH; u++) {
        if (u < us) continue;
        rmsum += rmx_s[u];

        float rp[8];
        #pragma unroll
        for (int j = 0; j < 8; j++) rp[j] = __shfl_xor_sync(FULL, R[j], 1);
        float ar[16];
        #pragma unroll
        for (int j = 0; j < 8; j++) {
            ar[j]   = h ? rp[j] : R[j];
            ar[j+8] = h ? R[j]  : rp[j];
        }

        float nw[8];
        #pragma unroll
        for (int kk2 = 0; kk2 < 8; kk2++) nw[kk2] = 0.f;
        #pragma unroll
        for (int j = 0; j < 16; j++) {
            const float4* pb = (const float4*)(&A_s[j*KK + h*8]);
            float4 b0 = pb[0], b1 = pb[1];
            float aj = ar[j];
            nw[0] = fmaf(aj, b0.x, nw[0]);
            nw[1] = fmaf(aj, b0.y, nw[1]);
            nw[2] = fmaf(aj, b0.z, nw[2]);
            nw[3] = fmaf(aj, b0.w, nw[3]);
            nw[4] = fmaf(aj, b1.x, nw[4]);
            nw[5] = fmaf(aj, b1.y, nw[5]);
            nw[6] = fmaf(aj, b1.z, nw[6]);
            nw[7] = fmaf(aj, b1.w, nw[7]);
        }
        const float4* pe = (const float4*)(&E_s[u*16 + h*8]);
        float4 e0 = pe[0], e1 = pe[1];
        R[0] = nw[0]*e0.x; R[1] = nw[1]*e0.y; R[2] = nw[2]*e0.z; R[3] = nw[3]*e0.w;
        R[4] = nw[4]*e1.x; R[5] = nw[5]*e1.y; R[6] = nw[6]*e1.z; R[7] = nw[7]*e1.w;

        if (((u + 1) & 7) == 0) {
            float mx = R[0];
            #pragma unroll
            for (int kk2 = 1; kk2 < 8; kk2++) mx = fmaxf(mx, R[kk2]);
            mx = fmaxf(mx, __shfl_xor_sync(FULL, mx, 1));
            mx = fmaxf(mx, 1e-37f);
            float inv = __fdividef(1.f, mx);
            #pragma unroll
            for (int kk2 = 0; kk2 < 8; kk2++) R[kk2] *= inv;
            rowlog += __logf(mx);
        }
    }

    #pragma unroll
    for (int kk2 = 0; kk2 < 8; kk2++)
        g_Rn[bid][iRow*KK + h*8 + kk2] = R[kk2];
    if (h == 0) g_rowlog[bid][iRow] = rowlog;
    if (lane == 0) g_rmsum[bid] = rmsum;
}

// ---------------------------------------------------------------------------
// Phase 2: one 256-thread block per batch (stage-in, super-combine,
// serial combine, boundary propagation).
// ---------------------------------------------------------------------------
__global__ void __launch_bounds__(256) phase2_kernel(const float* __restrict__ start_logits) {
    extern __shared__ __align__(16) float sm2[];
    float* Rs   = sm2;                 // [NC][256]
    float* rls  = Rs + NC*256;         // [NC][16]
    float* rms  = rls + NC*16;         // [NC]
    float* Ss   = rms + NC;            // [NSUP][256]
    float* srcv = Ss + NSUP*256;       // [NSUP]
    float* qs   = srcv + NSUP;         // [NSUP][16]
    float* Cs   = qs + NSUP*16;        // [NSUP]

    int b = blockIdx.x;
    int tid = threadIdx.x;
    int w = tid >> 5, lane = tid & 31;
    int kk = lane & 15;

    {
        const float4* src = (const float4*)(&g_Rn[b*NC][0]);
        float4* dst = (float4*)Rs;
        for (int i = tid; i < NC*64; i += 256) dst[i] = __ldg(src + i);
        const float4* s2 = (const float4*)(&g_rowlog[b*NC][0]);
        float4* d2 = (float4*)rls;
        for (int i = tid; i < NC*4; i += 256) d2[i] = __ldg(s2 + i);
        if (tid < NC) rms[tid] = __ldg(&g_rmsum[b*NC + tid]);
    }
    __syncthreads();

    int iRow = lane >> 1, h = lane & 1;

    #pragma unroll
    for (int ss2 = 0; ss2 < 2; ss2++) {
        int s = w + ss2*8;
        int c0 = s*SUPW;

        float acc[8];
        {
            const float4* p = (const float4*)(Rs + c0*256 + iRow*16 + h*8);
            float4 r0 = p[0], r1 = p[1];
            acc[0]=r0.x; acc[1]=r0.y; acc[2]=r0.z; acc[3]=r0.w;
            acc[4]=r1.x; acc[5]=r1.y; acc[6]=r1.z; acc[7]=r1.w;
        }
        float rlA = rls[c0*16 + iRow];

        for (int m = 1; m < SUPW; m++) {
            int cm = c0 + m;
            float rl = (lane < 16) ? rls[cm*16 + lane] : -3.4e38f;
            float rlmax = rl;
            #pragma unroll
            for (int off = 16; off; off >>= 1)
                rlmax = fmaxf(rlmax, __shfl_xor_sync(FULL, rlmax, off));
            float sB = __expf(rl - rlmax);

            float rp[8];
            #pragma unroll
            for (int j = 0; j < 8; j++) rp[j] = __shfl_xor_sync(FULL, acc[j], 1);
            float ar[16];
            #pragma unroll
            for (int j = 0; j < 8; j++) {
                ar[j]   = h ? rp[j]  : acc[j];
                ar[j+8] = h ? acc[j] : rp[j];
            }

            float nw[8];
            #pragma unroll
            for (int kk2 = 0; kk2 < 8; kk2++) nw[kk2] = 0.f;
            #pragma unroll
            for (int j = 0; j < 16; j++) {
                const float4* pb = (const float4*)(Rs + cm*256 + j*16 + h*8);
                float4 b0 = pb[0], b1 = pb[1];
                float aj = ar[j] * __shfl_sync(FULL, sB, j);
                nw[0] = fmaf(aj, b0.x, nw[0]);
                nw[1] = fmaf(aj, b0.y, nw[1]);
                nw[2] = fmaf(aj, b0.z, nw[2]);
                nw[3] = fmaf(aj, b0.w, nw[3]);
                nw[4] = fmaf(aj, b1.x, nw[4]);
                nw[5] = fmaf(aj, b1.y, nw[5]);
                nw[6] = fmaf(aj, b1.z, nw[6]);
                nw[7] = fmaf(aj, b1.w, nw[7]);
            }
            float mx = nw[0];
            #pragma unroll
            for (int kk2 = 1; kk2 < 8; kk2++) mx = fmaxf(mx, nw[kk2]);
            mx = fmaxf(mx, __shfl_xor_sync(FULL, mx, 1));
            mx = fmaxf(mx, 1e-37f);
            float inv = __fdividef(1.f, mx);
            #pragma unroll
            for (int kk2 = 0; kk2 < 8; kk2++) acc[kk2] = nw[kk2] * inv;
            rlA += rlmax + __logf(mx);
        }

        float srlmax = rlA;
        #pragma unroll
        for (int off = 16; off; off >>= 1)
            srlmax = fmaxf(srlmax, __shfl_xor_sync(FULL, srlmax, off));
        float rsc = __expf(rlA - srlmax);
        #pragma unroll
        for (int kk2 = 0; kk2 < 8; kk2++)
            Ss[s*256 + iRow*16 + h*8 + kk2] = acc[kk2] * rsc;
        if (lane == 0) {
            float t = 0.f;
            #pragma unroll
            for (int m = 0; m < SUPW; m++) t += rms[c0 + m];
            srcv[s] = t + srlmax;
        }
    }
    __syncthreads();

    if (w == 0) {
        float sv = __ldg(start_logits + kk);
        float sm = sv;
        #pragma unroll
        for (int off = 8; off; off >>= 1) sm = fmaxf(sm, __shfl_xor_sync(FULL, sm, off));
        float se = __expf(sv - sm);
        #pragma unroll
        for (int off = 8; off; off >>= 1) se += __shfl_xor_sync(FULL, se, off);
        float lstart = sv - sm - __logf(se);

        float e0 = __ldg(&g_emp[(size_t)(b*SS)*KK + kk]);
        float t = lstart + e0;
        float m0 = t;
        #pragma unroll
        for (int off = 8; off; off >>= 1) m0 = fmaxf(m0, __shfl_xor_sync(FULL, m0, off));
        float q = __expf(t - m0);
        float C = __ldg(&g_rowmax[b*SS]) + m0;

        float Bc[16], Bn[16];
        #pragma unroll
        for (int i = 0; i < 16; i++) Bc[i] = Ss[i*16 + kk];

        for (int c = 0; c < NSUP; c++) {
            if (c > 0) {
                if (lane < 16) qs[c*16 + kk] = q;
                if (lane == 0) Cs[c] = C;
            }
            if (c + 1 < NSUP) {
                #pragma unroll
                for (int i = 0; i < 16; i++) Bn[i] = Ss[(c+1)*256 + i*16 + kk];
            }
            float s0 = 0.f, s1 = 0.f, s2 = 0.f, s3 = 0.f;
            #pragma unroll
            for (int j = 0; j < 16; j += 4) {
                s0 = fmaf(__shfl_sync(FULL, q, j + 0), Bc[j + 0], s0);
                s1 = fmaf(__shfl_sync(FULL, q, j + 1), Bc[j + 1], s1);
                s2 = fmaf(__shfl_sync(FULL, q, j + 2), Bc[j + 2], s2);
                s3 = fmaf(__shfl_sync(FULL, q, j + 3), Bc[j + 3], s3);
            }
            float v = (s0 + s1) + (s2 + s3);
            C += srcv[c];
            if ((c & 7) == 7) {
                float mv = v;
                #pragma unroll
                for (int off = 8; off; off >>= 1)
                    mv = fmaxf(mv, __shfl_xor_sync(FULL, mv, off));
                mv = fmaxf(mv, 1e-37f);
                q = __fdividef(v, mv);
                C += __logf(mv);
            } else {
                q = v;
            }
            #pragma unroll
            for (int i = 0; i < 16; i++) Bc[i] = Bn[i];
        }
    }
    __syncthreads();

    #pragma unroll
    for (int ss2 = 0; ss2 < 2; ss2++) {
        int s = w + ss2*8;
        float q, C;
        if (s == 0) {
            float sv = __ldg(start_logits + kk);
            float sm = sv;
            #pragma unroll
            for (int off = 8; off; off >>= 1) sm = fmaxf(sm, __shfl_xor_sync(FULL, sm, off));
            float se = __expf(sv - sm);
            #pragma unroll
            for (int off = 8; off; off >>= 1) se += __shfl_xor_sync(FULL, se, off);
            float lstart = sv - sm - __logf(se);
            float e0 = __ldg(&g_emp[(size_t)(b*SS)*KK + kk]);
            float t = lstart + e0;
            float m0 = t;
            #pragma unroll
            for (int off = 8; off; off >>= 1) m0 = fmaxf(m0, __shfl_xor_sync(FULL, m0, off));
            q = __expf(t - m0);
            C = __ldg(&g_rowmax[b*SS]) + m0;
        } else {
            q = qs[s*16 + kk];
            C = Cs[s];
        }

        for (int m = 0; m < SUPW; m++) {
            int cl = s*SUPW + m;
            int gc = b*NC + cl;
            if (cl > 0) {
                if (lane < 16) g_qb[gc][kk] = q;
                if (lane == 0) g_Cb[gc] = C;
            }
            if (m + 1 < SUPW) {
                float rl = (lane < 16) ? rls[cl*16 + lane] : -3.4e38f;
                float rlmax = rl;
                #pragma unroll
                for (int off = 16; off; off >>= 1)
                    rlmax = fmaxf(rlmax, __shfl_xor_sync(FULL, rlmax, off));
                float smy = __expf(rl - rlmax);
                float qsc = q * smy;

                float s0 = 0.f, s1 = 0.f, s2 = 0.f, s3 = 0.f;
                #pragma unroll
                for (int j = 0; j < 16; j += 4) {
                    s0 = fmaf(__shfl_sync(FULL, qsc, j + 0), Rs[cl*256 + (j+0)*16 + kk], s0);
                    s1 = fmaf(__shfl_sync(FULL, qsc, j + 1), Rs[cl*256 + (j+1)*16 + kk], s1);
                    s2 = fmaf(__shfl_sync(FULL, qsc, j + 2), Rs[cl*256 + (j+2)*16 + kk], s2);
                    s3 = fmaf(__shfl_sync(FULL, qsc, j + 3), Rs[cl*256 + (j+3)*16 + kk], s3);
                }
                float v = (s0 + s1) + (s2 + s3);
                float mv = v;
                #pragma unroll
                for (int off = 8; off; off >>= 1)
                    mv = fmaxf(mv, __shfl_xor_sync(FULL, mv, off));
                mv = fmaxf(mv, 1e-37f);
                q = __fdividef(v, mv);
                C += rms[cl] + rlmax + __logf(mv);
            }
        }
    }
}

// ---------------------------------------------------------------------------
// Phase 3: per-chunk vector recursion; E recomputed from emp (no g_E).
// ---------------------------------------------------------------------------
__global__ void __launch_bounds__(32) phase3_kernel(
    const float* __restrict__ start_logits, float* __restrict__ out)
{
    int c = blockIdx.x;
    int lane = threadIdx.x;
    int b = c / NC, cl = c % NC;
    int kk = lane & 15;

    float acol[KK];
    #pragma unroll
    for (int j = 0; j < KK; j++) acol[j] = __ldg(&g_A[j*KK + kk]);

    const float* pP = g_emp + (size_t)(b*SS + cl*CH)*KK;
    const float* prm = g_rowmax + b*SS + cl*CH;
    float* ob = out + (size_t)(b*SS + cl*CH)*KK;

    float bufE[CH], bufP[CH], rm[CH];
    #pragma unroll
    for (int u = 0; u < CH; u++) {
        bufP[u] = __ldg(pP + u*KK + kk);
        rm[u]   = __ldg(prm + u);
        bufE[u] = __expf(fmaxf(bufP[u], -80.f));
    }

    float q, C;
    if (cl == 0) {
        float sv = __ldg(start_logits + kk);
        float sm = sv;
        #pragma unroll
        for (int off = 8; off; off >>= 1) sm = fmaxf(sm, __shfl_xor_sync(FULL, sm, off));
        float se = __expf(sv - sm);
        #pragma unroll
        for (int off = 8; off; off >>= 1) se += __shfl_xor_sync(FULL, se, off);
        float lstart = sv - sm - __logf(se);

        float a0 = lstart + bufP[0] + rm[0];
        if (lane < 16) ob[kk] = a0;
        q = __expf(fmaxf(lstart + bufP[0], -80.f));
        C = rm[0];
    } else {
        q = __ldg(&g_qb[c][kk]);
        C = __ldg(&g_Cb[c]);
    }

    #pragma unroll
    for (int u = 0; u < CH; u++) {
        if (cl == 0 && u == 0) continue;
        float s0 = 0.f, s1 = 0.f, s2 = 0.f, s3 = 0.f;
        #pragma unroll
        for (int j = 0; j < KK; j += 4) {
            s0 = fmaf(__shfl_sync(FULL, q, j + 0), acol[j + 0], s0);
            s1 = fmaf(__shfl_sync(FULL, q, j + 1), acol[j + 1], s1);
            s2 = fmaf(__shfl_sync(FULL, q, j + 2), acol[j + 2], s2);
            s3 = fmaf(__shfl_sync(FULL, q, j + 3), acol[j + 3], s3);
        }
        float ssum = (s0 + s1) + (s2 + s3);
        ssum = fmaxf(ssum, 1e-37f);
        float ov = C + rm[u] + bufP[u] + __logf(ssum);
        if (lane < 16) ob[u*KK + kk] = ov;
        q = ssum * bufE[u];
        C += rm[u];
    }
}

// ---------------------------------------------------------------------------
extern "C" void kernel_launch(void* const* d_in, const int* in_sizes, int n_in,
                              void* d_out, int out_size) {
    const float* y   = (const float*)d_in[0];
    const float* z   = (const float*)d_in[1];
    const float* st  = (const float*)d_in[2];
    const float* tr  = (const float*)d_in[3];
    const float* mu  = (const float*)d_in[4];
    const float* lv  = (const float*)d_in[5];
    const float* wz  = (const float*)d_in[6];
    const float* ws  = (const float*)d_in[7];
    const float* bd  = (const float*)d_in[8];
    float* out = (float*)d_out;

    int a_smem  = SM_TOTAL * sizeof(float);   // ~52 KB
    int p2_smem = (NC*256 + NC*16 + NC + NSUP*256 + NSUP + NSUP*16 + NSUP) * sizeof(float);
    cudaFuncSetAttribute(kernelA,
                         cudaFuncAttributeMaxDynamicSharedMemorySize, a_smem);
    cudaFuncSetAttribute(phase2_kernel,
                         cudaFuncAttributeMaxDynamicSharedMemorySize, p2_smem);

    kernelA<<<TOTCH, TPB, a_smem>>>(y, z, wz, ws, bd, lv, mu, tr);
    phase2_kernel<<<BB, 256, p2_smem>>>(st);
    phase3_kernel<<<TOTCH, 32>>>(st, out);
}

// round 11
// speedup vs baseline: 1.5776x; 1.5776x over previous
#include <cuda_runtime.h>

#define BB 16
#define SS 2048
#define KK 16
#define LL 64
#define II 256
#define NS (BB*SS)        // 32768
#define CH 16
#define NC (SS/CH)        // 128 chunks per batch
#define TOTCH (BB*NC)     // 2048
#define SUPW 8
#define NSUP (NC/SUPW)    // 16

#define SPB 16
#define TPB 256

#define FULL 0xffffffffu

// ---- packed f32x2 helpers ----
typedef unsigned long long u64t;
#define FMA2(d,a,b,c) asm volatile("fma.rn.f32x2 %0, %1, %2, %3;" : "=l"(d) : "l"(a), "l"(b), "l"(c))
#define ADD2(d,a,b)   asm volatile("add.rn.f32x2 %0, %1, %2;" : "=l"(d) : "l"(a), "l"(b))
#define MUL2(d,a,b)   asm volatile("mul.rn.f32x2 %0, %1, %2;" : "=l"(d) : "l"(a), "l"(b))
#define PK2(d,lo,hi)  asm volatile("mov.b64 %0, {%1, %2};" : "=l"(d) : "r"(lo), "r"(hi))
#define UPK2(lo,hi,s) asm volatile("mov.b64 {%0, %1}, %2;" : "=r"(lo), "=r"(hi) : "l"(s))
#define LDS2(a,b,addr) asm volatile("ld.shared.v2.u64 {%0, %1}, [%2];" : "=l"(a), "=l"(b) : "r"(addr))

__device__ __forceinline__ unsigned s2u(const void* p) {
    unsigned r;
    asm("{ .reg .u64 t; cvta.to.shared.u64 t, %1; cvt.u32.u64 %0, t; }" : "=r"(r) : "l"(p));
    return r;
}

// Scratch (device globals; no allocation allowed)
__device__ __align__(16) float g_d[(size_t)NS*II];    // 32 MB: d = y - base
__device__ __align__(16) float g_E[NS*KK];
__device__ __align__(16) float g_emp[NS*KK];
__device__ __align__(16) float g_rowmax[NS];
__device__ __align__(16) float g_invvar[KK*LL];
__device__ __align__(16) float g_nm[KK*LL];           // -mu
__device__ float g_lvsum[KK];
__device__ float g_ws2[KK];
__device__ float g_A[KK*KK];
__device__ __align__(16) float g_Rn[TOTCH][KK*KK];
__device__ __align__(16) float g_rowlog[TOTCH][KK];
__device__ __align__(16) float g_rmsum[TOTCH];
__device__ float g_qb[TOTCH][KK];
__device__ float g_Cb[TOTCH];

// ---------------------------------------------------------------------------
// Setup: one warp-block per state k.
// ---------------------------------------------------------------------------
__global__ void __launch_bounds__(32) setup_kernel(
    const float* __restrict__ prior_logvar,
    const float* __restrict__ Ws,
    const float* __restrict__ trans,
    const float* __restrict__ mu)
{
    int w = blockIdx.x;
    int lane = threadIdx.x;

    float s = 0.f;
    #pragma unroll
    for (int e = 0; e < 2; e++) {
        int idx = w*LL + lane + 32*e;
        float lv = __ldg(prior_logvar + idx);
        g_invvar[idx] = 1.0f / (expf(lv) + 1e-8f);
        g_nm[idx] = -__ldg(mu + idx);
        s += lv;
    }
    #pragma unroll
    for (int off = 16; off; off >>= 1) s += __shfl_xor_sync(FULL, s, off);
    if (lane == 0) g_lvsum[w] = s;

    float s2 = 0.f;
    #pragma unroll
    for (int e = 0; e < 8; e++) {
        float v = __ldg(Ws + w*II + lane + 32*e);
        s2 = fmaf(v, v, s2);
    }
    #pragma unroll
    for (int off = 16; off; off >>= 1) s2 += __shfl_xor_sync(FULL, s2, off);
    if (lane == 0) g_ws2[w] = s2;

    float v = (lane < 16) ? __ldg(trans + w*KK + (lane & 15)) : -1e30f;
    float mx = v;
    #pragma unroll
    for (int off = 8; off; off >>= 1) mx = fmaxf(mx, __shfl_xor_sync(FULL, mx, off));
    float ex = (lane < 16) ? expf(v - mx) : 0.f;
    float se = ex;
    #pragma unroll
    for (int off = 8; off; off >>= 1) se += __shfl_xor_sync(FULL, se, off);
    if (lane < 16) g_A[w*KK + lane] = expf(v - mx - logf(se));
}

// ---------------------------------------------------------------------------
// E1: d = y - (z @ Wz) - b_dec   (lean: 4KB smem, high occupancy)
// ---------------------------------------------------------------------------
__global__ void __launch_bounds__(TPB) e1_kernel(
    const float* __restrict__ Y, const float* __restrict__ Z,
    const float* __restrict__ Wz, const float* __restrict__ bdec)
{
    __shared__ __align__(16) float z_a[LL*SPB];   // [l][s], 4KB

    int tid = threadIdx.x;
    int s0 = blockIdx.x * SPB;

    #pragma unroll
    for (int e = 0; e < (SPB*LL)/TPB; e++) {
        int idx = tid + TPB*e;
        int s = idx >> 6, l = idx & 63;
        z_a[l*SPB + s] = Z[(s0 + s)*LL + l];
    }
    __syncthreads();

    u64t bp[8];
    float bd = __ldg(bdec + tid);
    u64t bdp; PK2(bdp, __float_as_uint(bd), __float_as_uint(bd));
    #pragma unroll
    for (int p = 0; p < 8; p++) bp[p] = bdp;

    unsigned za0 = s2u(z_a);
    #pragma unroll 4
    for (int l = 0; l < LL; l++) {
        float wz = __ldg(Wz + l*II + tid);
        u64t wzp; PK2(wzp, __float_as_uint(wz), __float_as_uint(wz));
        unsigned row = za0 + l*(SPB*4);
        u64t z0,z1,z2,z3,z4,z5,z6,z7;
        LDS2(z0, z1, row);
        LDS2(z2, z3, row + 16);
        LDS2(z4, z5, row + 32);
        LDS2(z6, z7, row + 48);
        FMA2(bp[0], z0, wzp, bp[0]);
        FMA2(bp[1], z1, wzp, bp[1]);
        FMA2(bp[2], z2, wzp, bp[2]);
        FMA2(bp[3], z3, wzp, bp[3]);
        FMA2(bp[4], z4, wzp, bp[4]);
        FMA2(bp[5], z5, wzp, bp[5]);
        FMA2(bp[6], z6, wzp, bp[6]);
        FMA2(bp[7], z7, wzp, bp[7]);
    }
    #pragma unroll
    for (int p = 0; p < 8; p++) {
        unsigned u0, u1; UPK2(u0, u1, bp[p]);
        int s = 2*p;
        float y0 = __ldg(Y + (size_t)(s0 + s)*II + tid);
        float y1 = __ldg(Y + (size_t)(s0 + s + 1)*II + tid);
        g_d[(size_t)(s0 + s)*II + tid]     = y0 - __uint_as_float(u0);
        g_d[(size_t)(s0 + s + 1)*II + tid] = y1 - __uint_as_float(u1);
    }
}

// ---------------------------------------------------------------------------
// E2: emissions from staged d (R8 phase B verbatim)
// ---------------------------------------------------------------------------
__global__ void __launch_bounds__(TPB) e2_kernel(
    const float* __restrict__ Z, const float* __restrict__ Ws)
{
    __shared__ __align__(16) float z_b[SPB][LL+4];
    __shared__ __align__(16) float d_sh[SPB][II];
    __shared__ __align__(16) float ws_sh[KK][II+4];

    int tid = threadIdx.x;
    int s0 = blockIdx.x * SPB;

    // stage d (coalesced float4)
    {
        const float4* src = (const float4*)(g_d + (size_t)s0*II);
        float4* dst = (float4*)&d_sh[0][0];
        #pragma unroll
        for (int e = 0; e < 4; e++) dst[tid + TPB*e] = __ldg(src + tid + TPB*e);
    }
    #pragma unroll
    for (int e = 0; e < (SPB*LL)/TPB; e++) {
        int idx = tid + TPB*e;
        int s = idx >> 6, l = idx & 63;
        z_b[s][l] = Z[(s0 + s)*LL + l];
    }
    #pragma unroll
    for (int e = 0; e < (KK*II)/TPB; e++) {
        int idx = tid + TPB*e;
        ws_sh[idx >> 8][idx & 255] = Ws[idx];
    }
    __syncthreads();

    int si = tid >> 4;
    int k  = tid & 15;

    float sd = 0.f;
    #pragma unroll
    for (int t = 0; t < 16; t++) {
        float dv = d_sh[si][t*16 + k];
        sd = fmaf(dv, dv, sd);
    }
    #pragma unroll
    for (int off = 8; off; off >>= 1) sd += __shfl_xor_sync(FULL, sd, off);

    float dot;
    {
        unsigned drow = s2u(&d_sh[si][0]);
        unsigned wrow = s2u(&ws_sh[k][0]);
        u64t a0 = 0ull, a1 = 0ull;
        #pragma unroll 8
        for (int i = 0; i < II/4; i++) {
            u64t d0, d1, w0, w1;
            LDS2(d0, d1, drow + i*16);
            LDS2(w0, w1, wrow + i*16);
            FMA2(a0, d0, w0, a0);
            FMA2(a1, d1, w1, a1);
        }
        unsigned l0, h0, l1, h1;
        UPK2(l0, h0, a0); UPK2(l1, h1, a1);
        dot = (__uint_as_float(l0) + __uint_as_float(h0))
            + (__uint_as_float(l1) + __uint_as_float(h1));
    }
    float accy = sd - 2.f*dot + __ldg(&g_ws2[k]);

    float accz;
    {
        unsigned zrow = s2u(&z_b[si][0]);
        const ulonglong2* nm2 = (const ulonglong2*)(g_nm + k*LL);
        const ulonglong2* iv2 = (const ulonglong2*)(g_invvar + k*LL);
        u64t a0 = 0ull, a1 = 0ull;
        #pragma unroll
        for (int i = 0; i < LL/4; i++) {
            u64t z0, z1;
            LDS2(z0, z1, zrow + i*16);
            ulonglong2 mv = __ldg(nm2 + i);
            ulonglong2 vv = __ldg(iv2 + i);
            u64t t0, t1;
            ADD2(t0, z0, mv.x);
            ADD2(t1, z1, mv.y);
            MUL2(t0, t0, t0);
            MUL2(t1, t1, t1);
            FMA2(a0, t0, vv.x, a0);
            FMA2(a1, t1, vv.y, a1);
        }
        unsigned l0, h0, l1, h1;
        UPK2(l0, h0, a0); UPK2(l1, h1, a1);
        accz = (__uint_as_float(l0) + __uint_as_float(h0))
             + (__uint_as_float(l1) + __uint_as_float(h1));
    }

    const float LLOG2PI = 117.62413f;  // 64 * log(2*pi)
    float em = -0.5f*accy - 0.5f*(__ldg(&g_lvsum[k]) + accz + LLOG2PI);

    float m = em;
    #pragma unroll
    for (int off = 8; off; off >>= 1)
        m = fmaxf(m, __shfl_xor_sync(FULL, m, off));

    float emp = em - m;
    float E = __expf(fmaxf(emp, -80.f));

    int sample = s0 + si;
    g_E[sample*KK + k]   = E;
    g_emp[sample*KK + k] = emp;
    if (k == 0) g_rowmax[sample] = m;
}

// ---------------------------------------------------------------------------
// Phase 1: per-chunk (16 steps) matrix product (R8 standalone, verbatim)
// ---------------------------------------------------------------------------
__global__ void __launch_bounds__(32) phase1_kernel() {
    int c = blockIdx.x;
    int lane = threadIdx.x;
    int b = c / NC, cl = c % NC;
    int i = lane >> 1, h = lane & 1;

    float a[KK][8];
    #pragma unroll
    for (int j = 0; j < KK; j++)
        #pragma unroll
        for (int kk = 0; kk < 8; kk++)
            a[j][kk] = g_A[j*KK + h*8 + kk];

    float R[8];
    #pragma unroll
    for (int kk = 0; kk < 8; kk++)
        R[kk] = (i == h*8 + kk) ? 1.f : 0.f;

    float rowlog = 0.f, rmsum = 0.f;

    int t0 = b*SS + cl*CH;
    int us = (cl == 0) ? 1 : 0;
    const float* prm = g_rowmax + t0;

    float E[8], En[8];
    {
        const float4* p4 = (const float4*)(g_E + (size_t)(t0 + us)*KK + h*8);
        float4 q0 = __ldg(p4+0), q1 = __ldg(p4+1);
        E[0]=q0.x; E[1]=q0.y; E[2]=q0.z; E[3]=q0.w;
        E[4]=q1.x; E[5]=q1.y; E[6]=q1.z; E[7]=q1.w;
    }
    float rmc = __ldg(prm + us), rmn = 0.f;

    #pragma unroll
    for (int u = 0; u < CH; u++) {
        if (u < us) continue;
        if (u + 1 < CH) {
            const float4* p4 = (const float4*)(g_E + (size_t)(t0 + u + 1)*KK + h*8);
            float4 q0 = __ldg(p4+0), q1 = __ldg(p4+1);
            En[0]=q0.x; En[1]=q0.y; En[2]=q0.z; En[3]=q0.w;
            En[4]=q1.x; En[5]=q1.y; En[6]=q1.z; En[7]=q1.w;
            rmn = __ldg(prm + u + 1);
        }
        rmsum += rmc;

        float rp[8];
        #pragma unroll
        for (int j = 0; j < 8; j++) rp[j] = __shfl_xor_sync(FULL, R[j], 1);
        float rlo[8], rhi[8];
        #pragma unroll
        for (int j = 0; j < 8; j++) {
            rlo[j] = h ? rp[j] : R[j];
            rhi[j] = h ? R[j] : rp[j];
        }
        float nw[8];
        #pragma unroll
        for (int kk = 0; kk < 8; kk++) {
            float s0 = 0.f, s1 = 0.f;
            #pragma unroll
            for (int j = 0; j < 8; j++) {
                s0 = fmaf(rlo[j], a[j][kk],   s0);
                s1 = fmaf(rhi[j], a[j+8][kk], s1);
            }
            nw[kk] = (s0 + s1) * E[kk];
        }
        #pragma unroll
        for (int kk = 0; kk < 8; kk++) R[kk] = nw[kk];

        if (((u + 1) & 7) == 0) {
            float mx = R[0];
            #pragma unroll
            for (int kk = 1; kk < 8; kk++) mx = fmaxf(mx, R[kk]);
            mx = fmaxf(mx, __shfl_xor_sync(FULL, mx, 1));
            mx = fmaxf(mx, 1e-37f);
            float inv = __fdividef(1.f, mx);
            #pragma unroll
            for (int kk = 0; kk < 8; kk++) R[kk] *= inv;
            rowlog += __logf(mx);
        }

        #pragma unroll
        for (int kk = 0; kk < 8; kk++) E[kk] = En[kk];
        rmc = rmn;
    }

    #pragma unroll
    for (int kk = 0; kk < 8; kk++)
        g_Rn[c][i*KK + h*8 + kk] = R[kk];
    if (h == 0) g_rowlog[c][i] = rowlog;
    if (lane == 0) g_rmsum[c] = rmsum;
}

// ---------------------------------------------------------------------------
// Phase 2: one 256-thread block per batch (R10 verbatim — proven correct)
// ---------------------------------------------------------------------------
__global__ void __launch_bounds__(256) phase2_kernel(const float* __restrict__ start_logits) {
    extern __shared__ __align__(16) float sm2[];
    float* Rs   = sm2;                 // [NC][256]
    float* rls  = Rs + NC*256;         // [NC][16]
    float* rms  = rls + NC*16;         // [NC]
    float* Ss   = rms + NC;            // [NSUP][256]
    float* srcv = Ss + NSUP*256;       // [NSUP]
    float* qs   = srcv + NSUP;         // [NSUP][16]
    float* Cs   = qs + NSUP*16;        // [NSUP]

    int b = blockIdx.x;
    int tid = threadIdx.x;
    int w = tid >> 5, lane = tid & 31;
    int kk = lane & 15;

    {
        const float4* src = (const float4*)(&g_Rn[b*NC][0]);
        float4* dst = (float4*)Rs;
        for (int i = tid; i < NC*64; i += 256) dst[i] = __ldg(src + i);
        const float4* s2 = (const float4*)(&g_rowlog[b*NC][0]);
        float4* d2 = (float4*)rls;
        for (int i = tid; i < NC*4; i += 256) d2[i] = __ldg(s2 + i);
        if (tid < NC) rms[tid] = __ldg(&g_rmsum[b*NC + tid]);
    }
    __syncthreads();

    int iRow = lane >> 1, h = lane & 1;

    #pragma unroll
    for (int ss2 = 0; ss2 < 2; ss2++) {
        int s = w + ss2*8;
        int c0 = s*SUPW;

        float acc[8];
        {
            const float4* p = (const float4*)(Rs + c0*256 + iRow*16 + h*8);
            float4 r0 = p[0], r1 = p[1];
            acc[0]=r0.x; acc[1]=r0.y; acc[2]=r0.z; acc[3]=r0.w;
            acc[4]=r1.x; acc[5]=r1.y; acc[6]=r1.z; acc[7]=r1.w;
        }
        float rlA = rls[c0*16 + iRow];

        for (int m = 1; m < SUPW; m++) {
            int cm = c0 + m;
            float rl = (lane < 16) ? rls[cm*16 + lane] : -3.4e38f;
            float rlmax = rl;
            #pragma unroll
            for (int off = 16; off; off >>= 1)
                rlmax = fmaxf(rlmax, __shfl_xor_sync(FULL, rlmax, off));
            float sB = __expf(rl - rlmax);

            float rp[8];
            #pragma unroll
            for (int j = 0; j < 8; j++) rp[j] = __shfl_xor_sync(FULL, acc[j], 1);
            float ar[16];
            #pragma unroll
            for (int j = 0; j < 8; j++) {
                ar[j]   = h ? rp[j]  : acc[j];
                ar[j+8] = h ? acc[j] : rp[j];
            }

            float nw[8];
            #pragma unroll
            for (int kk2 = 0; kk2 < 8; kk2++) nw[kk2] = 0.f;
            #pragma unroll
            for (int j = 0; j < 16; j++) {
                const float4* pb = (const float4*)(Rs + cm*256 + j*16 + h*8);
                float4 b0 = pb[0], b1 = pb[1];
                float aj = ar[j] * __shfl_sync(FULL, sB, j);
                nw[0] = fmaf(aj, b0.x, nw[0]);
                nw[1] = fmaf(aj, b0.y, nw[1]);
                nw[2] = fmaf(aj, b0.z, nw[2]);
                nw[3] = fmaf(aj, b0.w, nw[3]);
                nw[4] = fmaf(aj, b1.x, nw[4]);
                nw[5] = fmaf(aj, b1.y, nw[5]);
                nw[6] = fmaf(aj, b1.z, nw[6]);
                nw[7] = fmaf(aj, b1.w, nw[7]);
            }
            float mx = nw[0];
            #pragma unroll
            for (int kk2 = 1; kk2 < 8; kk2++) mx = fmaxf(mx, nw[kk2]);
            mx = fmaxf(mx, __shfl_xor_sync(FULL, mx, 1));
            mx = fmaxf(mx, 1e-37f);
            float inv = __fdividef(1.f, mx);
            #pragma unroll
            for (int kk2 = 0; kk2 < 8; kk2++) acc[kk2] = nw[kk2] * inv;
            rlA += rlmax + __logf(mx);
        }

        float srlmax = rlA;
        #pragma unroll
        for (int off = 16; off; off >>= 1)
            srlmax = fmaxf(srlmax, __shfl_xor_sync(FULL, srlmax, off));
        float rsc = __expf(rlA - srlmax);
        #pragma unroll
        for (int kk2 = 0; kk2 < 8; kk2++)
            Ss[s*256 + iRow*16 + h*8 + kk2] = acc[kk2] * rsc;
        if (lane == 0) {
            float t = 0.f;
            #pragma unroll
            for (int m = 0; m < SUPW; m++) t += rms[c0 + m];
            srcv[s] = t + srlmax;
        }
    }
    __syncthreads();

    if (w == 0) {
        float sv = __ldg(start_logits + kk);
        float sm = sv;
        #pragma unroll
        for (int off = 8; off; off >>= 1) sm = fmaxf(sm, __shfl_xor_sync(FULL, sm, off));
        float se = __expf(sv - sm);
        #pragma unroll
        for (int off = 8; off; off >>= 1) se += __shfl_xor_sync(FULL, se, off);
        float lstart = sv - sm - __logf(se);

        float e0 = __ldg(&g_emp[(size_t)(b*SS)*KK + kk]);
        float t = lstart + e0;
        float m0 = t;
        #pragma unroll
        for (int off = 8; off; off >>= 1) m0 = fmaxf(m0, __shfl_xor_sync(FULL, m0, off));
        float q = __expf(t - m0);
        float C = __ldg(&g_rowmax[b*SS]) + m0;

        float Bc[16], Bn[16];
        #pragma unroll
        for (int i = 0; i < 16; i++) Bc[i] = Ss[i*16 + kk];

        for (int c = 0; c < NSUP; c++) {
            if (c > 0) {
                if (lane < 16) qs[c*16 + kk] = q;
                if (lane == 0) Cs[c] = C;
            }
            if (c + 1 < NSUP) {
                #pragma unroll
                for (int i = 0; i < 16; i++) Bn[i] = Ss[(c+1)*256 + i*16 + kk];
            }
            float s0 = 0.f, s1 = 0.f, s2 = 0.f, s3 = 0.f;
            #pragma unroll
            for (int j = 0; j < 16; j += 4) {
                s0 = fmaf(__shfl_sync(FULL, q, j + 0), Bc[j + 0], s0);
                s1 = fmaf(__shfl_sync(FULL, q, j + 1), Bc[j + 1], s1);
                s2 = fmaf(__shfl_sync(FULL, q, j + 2), Bc[j + 2], s2);
                s3 = fmaf(__shfl_sync(FULL, q, j + 3), Bc[j + 3], s3);
            }
            float v = (s0 + s1) + (s2 + s3);
            C += srcv[c];
            if ((c & 7) == 7) {
                float mv = v;
                #pragma unroll
                for (int off = 8; off; off >>= 1)
                    mv = fmaxf(mv, __shfl_xor_sync(FULL, mv, off));
                mv = fmaxf(mv, 1e-37f);
                q = __fdividef(v, mv);
                C += __logf(mv);
            } else {
                q = v;
            }
            #pragma unroll
            for (int i = 0; i < 16; i++) Bc[i] = Bn[i];
        }
    }
    __syncthreads();

    #pragma unroll
    for (int ss2 = 0; ss2 < 2; ss2++) {
        int s = w + ss2*8;
        float q, C;
        if (s == 0) {
            float sv = __ldg(start_logits + kk);
            float sm = sv;
            #pragma unroll
            for (int off = 8; off; off >>= 1) sm = fmaxf(sm, __shfl_xor_sync(FULL, sm, off));
            float se = __expf(sv - sm);
            #pragma unroll
            for (int off = 8; off; off >>= 1) se += __shfl_xor_sync(FULL, se, off);
            float lstart = sv - sm - __logf(se);
            float e0 = __ldg(&g_emp[(size_t)(b*SS)*KK + kk]);
            float t = lstart + e0;
            float m0 = t;
            #pragma unroll
            for (int off = 8; off; off >>= 1) m0 = fmaxf(m0, __shfl_xor_sync(FULL, m0, off));
            q = __expf(t - m0);
            C = __ldg(&g_rowmax[b*SS]) + m0;
        } else {
            q = qs[s*16 + kk];
            C = Cs[s];
        }

        for (int m = 0; m < SUPW; m++) {
            int cl = s*SUPW + m;
            int gc = b*NC + cl;
            if (cl > 0) {
                if (lane < 16) g_qb[gc][kk] = q;
                if (lane == 0) g_Cb[gc] = C;
            }
            if (m + 1 < SUPW) {
                float rl = (lane < 16) ? rls[cl*16 + lane] : -3.4e38f;
                float rlmax = rl;
                #pragma unroll
                for (int off = 16; off; off >>= 1)
                    rlmax = fmaxf(rlmax, __shfl_xor_sync(FULL, rlmax, off));
                float smy = __expf(rl - rlmax);
                float qsc = q * smy;

                float s0 = 0.f, s1 = 0.f, s2 = 0.f, s3 = 0.f;
                #pragma unroll
                for (int j = 0; j < 16; j += 4) {
                    s0 = fmaf(__shfl_sync(FULL, qsc, j + 0), Rs[cl*256 + (j+0)*16 + kk], s0);
                    s1 = fmaf(__shfl_sync(FULL, qsc, j + 1), Rs[cl*256 + (j+1)*16 + kk], s1);
                    s2 = fmaf(__shfl_sync(FULL, qsc, j + 2), Rs[cl*256 + (j+2)*16 + kk], s2);
                    s3 = fmaf(__shfl_sync(FULL, qsc, j + 3), Rs[cl*256 + (j+3)*16 + kk], s3);
                }
                float v = (s0 + s1) + (s2 + s3);
                float mv = v;
                #pragma unroll
                for (int off = 8; off; off >>= 1)
                    mv = fmaxf(mv, __shfl_xor_sync(FULL, mv, off));
                mv = fmaxf(mv, 1e-37f);
                q = __fdividef(v, mv);
                C += rms[cl] + rlmax + __logf(mv);
            }
        }
    }
}

// ---------------------------------------------------------------------------
// Phase 3: per-chunk vector recursion (R10 verbatim — E recomputed from emp)
// ---------------------------------------------------------------------------
__global__ void __launch_bounds__(32) phase3_kernel(
    const float* __restrict__ start_logits, float* __restrict__ out)
{
    int c = blockIdx.x;
    int lane = threadIdx.x;
    int b = c / NC, cl = c % NC;
    int kk = lane & 15;

    float acol[KK];
    #pragma unroll
    for (int j = 0; j < KK; j++) acol[j] = __ldg(&g_A[j*KK + kk]);

    const float* pP = g_emp + (size_t)(b*SS + cl*CH)*KK;
    const float* prm = g_rowmax + b*SS + cl*CH;
    float* ob = out + (size_t)(b*SS + cl*CH)*KK;

    float bufE[CH], bufP[CH], rm[CH];
    #pragma unroll
    for (int u = 0; u < CH; u++) {
        bufP[u] = __ldg(pP + u*KK + kk);
        rm[u]   = __ldg(prm + u);
        bufE[u] = __expf(fmaxf(bufP[u], -80.f));
    }

    float q, C;
    if (cl == 0) {
        float sv = __ldg(start_logits + kk);
        float sm = sv;
        #pragma unroll
        for (int off = 8; off; off >>= 1) sm = fmaxf(sm, __shfl_xor_sync(FULL, sm, off));
        float se = __expf(sv - sm);
        #pragma unroll
        for (int off = 8; off; off >>= 1) se += __shfl_xor_sync(FULL, se, off);
        float lstart = sv - sm - __logf(se);

        float a0 = lstart + bufP[0] + rm[0];
        if (lane < 16) ob[kk] = a0;
        q = __expf(fmaxf(lstart + bufP[0], -80.f));
        C = rm[0];
    } else {
        q = __ldg(&g_qb[c][kk]);
        C = __ldg(&g_Cb[c]);
    }

    #pragma unroll
    for (int u = 0; u < CH; u++) {
        if (cl == 0 && u == 0) continue;
        float s0 = 0.f, s1 = 0.f, s2 = 0.f, s3 = 0.f;
        #pragma unroll
        for (int j = 0; j < KK; j += 4) {
            s0 = fmaf(__shfl_sync(FULL, q, j + 0), acol[j + 0], s0);
            s1 = fmaf(__shfl_sync(FULL, q, j + 1), acol[j + 1], s1);
            s2 = fmaf(__shfl_sync(FULL, q, j + 2), acol[j + 2], s2);
            s3 = fmaf(__shfl_sync(FULL, q, j + 3), acol[j + 3], s3);
        }
        float ssum = (s0 + s1) + (s2 + s3);
        ssum = fmaxf(ssum, 1e-37f);
        float ov = C + rm[u] + bufP[u] + __logf(ssum);
        if (lane < 16) ob[u*KK + kk] = ov;
        q = ssum * bufE[u];
        C += rm[u];
    }
}

// ---------------------------------------------------------------------------
extern "C" void kernel_launch(void* const* d_in, const int* in_sizes, int n_in,
                              void* d_out, int out_size) {
    const float* y   = (const float*)d_in[0];
    const float* z   = (const float*)d_in[1];
    const float* st  = (const float*)d_in[2];
    const float* tr  = (const float*)d_in[3];
    const float* mu  = (const float*)d_in[4];
    const float* lv  = (const float*)d_in[5];
    const float* wz  = (const float*)d_in[6];
    const float* ws  = (const float*)d_in[7];
    const float* bd  = (const float*)d_in[8];
    float* out = (float*)d_out;

    int p2_smem = (NC*256 + NC*16 + NC + NSUP*256 + NSUP + NSUP*16 + NSUP) * sizeof(float);
    cudaFuncSetAttribute(phase2_kernel,
                         cudaFuncAttributeMaxDynamicSharedMemorySize, p2_smem);

    setup_kernel<<<KK, 32>>>(lv, ws, tr, mu);
    e1_kernel<<<NS/SPB, TPB>>>(y, z, wz, bd);
    e2_kernel<<<NS/SPB, TPB>>>(z, ws);
    phase1_kernel<<<TOTCH, 32>>>();
    phase2_kernel<<<BB, 256, p2_smem>>>(st);
    phase3_kernel<<<TOTCH, 32>>>(st, out);
}

// round 12
// speedup vs baseline: 1.6761x; 1.0624x over previous
#include <cuda_runtime.h>

#define BB 16
#define SS 2048
#define KK 16
#define LL 64
#define II 256
#define NS (BB*SS)        // 32768
#define CH 16
#define NC (SS/CH)        // 128 chunks per batch
#define TOTCH (BB*NC)     // 2048
#define SUPW 8
#define NSUP (NC/SUPW)    // 16

#define SPB 16
#define TPB 256

#define FULL 0xffffffffu

// ---- packed f32x2 helpers ----
typedef unsigned long long u64t;
#define FMA2(d,a,b,c) asm volatile("fma.rn.f32x2 %0, %1, %2, %3;" : "=l"(d) : "l"(a), "l"(b), "l"(c))
#define ADD2(d,a,b)   asm volatile("add.rn.f32x2 %0, %1, %2;" : "=l"(d) : "l"(a), "l"(b))
#define MUL2(d,a,b)   asm volatile("mul.rn.f32x2 %0, %1, %2;" : "=l"(d) : "l"(a), "l"(b))
#define PK2(d,lo,hi)  asm volatile("mov.b64 %0, {%1, %2};" : "=l"(d) : "r"(lo), "r"(hi))
#define UPK2(lo,hi,s) asm volatile("mov.b64 {%0, %1}, %2;" : "=r"(lo), "=r"(hi) : "l"(s))
#define LDS2(a,b,addr) asm volatile("ld.shared.v2.u64 {%0, %1}, [%2];" : "=l"(a), "=l"(b) : "r"(addr))

__device__ __forceinline__ unsigned s2u(const void* p) {
    unsigned r;
    asm("{ .reg .u64 t; cvta.to.shared.u64 t, %1; cvt.u32.u64 %0, t; }" : "=r"(r) : "l"(p));
    return r;
}

// Scratch (device globals; no allocation allowed)
__device__ __align__(16) float g_E[NS*KK];
__device__ __align__(16) float g_emp[NS*KK];
__device__ __align__(16) float g_rowmax[NS];
__device__ __align__(16) float g_invvar[KK*LL];
__device__ __align__(16) float g_nm[KK*LL];           // -mu
__device__ float g_lvsum[KK];
__device__ float g_ws2[KK];
__device__ __align__(16) float g_A[KK*KK];
__device__ __align__(16) float g_Rn[TOTCH][KK*KK];
__device__ __align__(16) float g_rowlog[TOTCH][KK];
__device__ __align__(16) float g_rmsum[TOTCH];
__device__ float g_qb[TOTCH][KK];
__device__ float g_Cb[TOTCH];

// ---------------------------------------------------------------------------
// Setup: one warp-block per state k.
// ---------------------------------------------------------------------------
__global__ void __launch_bounds__(32) setup_kernel(
    const float* __restrict__ prior_logvar,
    const float* __restrict__ Ws,
    const float* __restrict__ trans,
    const float* __restrict__ mu)
{
    int w = blockIdx.x;
    int lane = threadIdx.x;

    float s = 0.f;
    #pragma unroll
    for (int e = 0; e < 2; e++) {
        int idx = w*LL + lane + 32*e;
        float lv = __ldg(prior_logvar + idx);
        g_invvar[idx] = 1.0f / (expf(lv) + 1e-8f);
        g_nm[idx] = -__ldg(mu + idx);
        s += lv;
    }
    #pragma unroll
    for (int off = 16; off; off >>= 1) s += __shfl_xor_sync(FULL, s, off);
    if (lane == 0) g_lvsum[w] = s;

    float s2 = 0.f;
    #pragma unroll
    for (int e = 0; e < 8; e++) {
        float v = __ldg(Ws + w*II + lane + 32*e);
        s2 = fmaf(v, v, s2);
    }
    #pragma unroll
    for (int off = 16; off; off >>= 1) s2 += __shfl_xor_sync(FULL, s2, off);
    if (lane == 0) g_ws2[w] = s2;

    float v = (lane < 16) ? __ldg(trans + w*KK + (lane & 15)) : -1e30f;
    float mx = v;
    #pragma unroll
    for (int off = 8; off; off >>= 1) mx = fmaxf(mx, __shfl_xor_sync(FULL, mx, off));
    float ex = (lane < 16) ? expf(v - mx) : 0.f;
    float se = ex;
    #pragma unroll
    for (int off = 8; off; off >>= 1) se += __shfl_xor_sync(FULL, se, off);
    if (lane < 16) g_A[w*KK + lane] = expf(v - mx - logf(se));
}

// ---------------------------------------------------------------------------
// Emissions (R8 structure; launch_bounds caps regs at 64 -> 4 blocks/SM)
// ---------------------------------------------------------------------------
__global__ void __launch_bounds__(TPB, 4) emissions_kernel(
    const float* __restrict__ Y, const float* __restrict__ Z,
    const float* __restrict__ Wz, const float* __restrict__ Ws,
    const float* __restrict__ bdec)
{
    __shared__ __align__(16) float z_a[LL][SPB];      // [l][s]
    __shared__ __align__(16) float z_b[SPB][LL+4];    // [s][l] padded (272B rows)
    __shared__ __align__(16) float d_sh[SPB][II];
    __shared__ __align__(16) float ws_sh[KK][II+4];   // 1040B rows

    int tid = threadIdx.x;
    int s0 = blockIdx.x * SPB;

    #pragma unroll
    for (int e = 0; e < (SPB*LL)/TPB; e++) {
        int idx = tid + TPB*e;
        int s = idx >> 6, l = idx & 63;
        float v = Z[(s0 + s)*LL + l];
        z_a[l][s] = v;
        z_b[s][l] = v;
    }
    #pragma unroll
    for (int e = 0; e < (KK*II)/TPB; e++) {
        int idx = tid + TPB*e;
        ws_sh[idx >> 8][idx & 255] = Ws[idx];
    }
    __syncthreads();

    // ---- Phase A: base = b_dec + z @ Wz (packed over sample pairs) ----
    {
        u64t bp[8];
        float bd = __ldg(bdec + tid);
        u64t bdp; PK2(bdp, __float_as_uint(bd), __float_as_uint(bd));
        #pragma unroll
        for (int p = 0; p < 8; p++) bp[p] = bdp;

        unsigned za0 = s2u(&z_a[0][0]);
        #pragma unroll 4
        for (int l = 0; l < LL; l++) {
            float wz = __ldg(Wz + l*II + tid);
            u64t wzp; PK2(wzp, __float_as_uint(wz), __float_as_uint(wz));
            unsigned row = za0 + l*(SPB*4);
            u64t z0,z1,z2,z3,z4,z5,z6,z7;
            LDS2(z0, z1, row);
            LDS2(z2, z3, row + 16);
            LDS2(z4, z5, row + 32);
            LDS2(z6, z7, row + 48);
            FMA2(bp[0], z0, wzp, bp[0]);
            FMA2(bp[1], z1, wzp, bp[1]);
            FMA2(bp[2], z2, wzp, bp[2]);
            FMA2(bp[3], z3, wzp, bp[3]);
            FMA2(bp[4], z4, wzp, bp[4]);
            FMA2(bp[5], z5, wzp, bp[5]);
            FMA2(bp[6], z6, wzp, bp[6]);
            FMA2(bp[7], z7, wzp, bp[7]);
        }
        #pragma unroll
        for (int p = 0; p < 8; p++) {
            unsigned u0, u1; UPK2(u0, u1, bp[p]);
            int s = 2*p;
            float y0 = __ldg(Y + (size_t)(s0 + s)*II + tid);
            float y1 = __ldg(Y + (size_t)(s0 + s + 1)*II + tid);
            d_sh[s][tid]     = y0 - __uint_as_float(u0);
            d_sh[s + 1][tid] = y1 - __uint_as_float(u1);
        }
    }
    __syncthreads();

    // ---- Phase B: thread (sample si, state k) ----
    int si = tid >> 4;
    int k  = tid & 15;

    float sd = 0.f;
    #pragma unroll
    for (int t = 0; t < 16; t++) {
        float dv = d_sh[si][t*16 + k];
        sd = fmaf(dv, dv, sd);
    }
    #pragma unroll
    for (int off = 8; off; off >>= 1) sd += __shfl_xor_sync(FULL, sd, off);

    float dot;
    {
        unsigned drow = s2u(&d_sh[si][0]);
        unsigned wrow = s2u(&ws_sh[k][0]);
        u64t a0 = 0ull, a1 = 0ull;
        #pragma unroll 8
        for (int i = 0; i < II/4; i++) {
            u64t d0, d1, w0, w1;
            LDS2(d0, d1, drow + i*16);
            LDS2(w0, w1, wrow + i*16);
            FMA2(a0, d0, w0, a0);
            FMA2(a1, d1, w1, a1);
        }
        unsigned l0, h0, l1, h1;
        UPK2(l0, h0, a0); UPK2(l1, h1, a1);
        dot = (__uint_as_float(l0) + __uint_as_float(h0))
            + (__uint_as_float(l1) + __uint_as_float(h1));
    }
    float accy = sd - 2.f*dot + __ldg(&g_ws2[k]);

    float accz;
    {
        unsigned zrow = s2u(&z_b[si][0]);
        const ulonglong2* nm2 = (const ulonglong2*)(g_nm + k*LL);
        const ulonglong2* iv2 = (const ulonglong2*)(g_invvar + k*LL);
        u64t a0 = 0ull, a1 = 0ull;
        #pragma unroll
        for (int i = 0; i < LL/4; i++) {
            u64t z0, z1;
            LDS2(z0, z1, zrow + i*16);
            ulonglong2 mv = __ldg(nm2 + i);
            ulonglong2 vv = __ldg(iv2 + i);
            u64t t0, t1;
            ADD2(t0, z0, mv.x);
            ADD2(t1, z1, mv.y);
            MUL2(t0, t0, t0);
            MUL2(t1, t1, t1);
            FMA2(a0, t0, vv.x, a0);
            FMA2(a1, t1, vv.y, a1);
        }
        unsigned l0, h0, l1, h1;
        UPK2(l0, h0, a0); UPK2(l1, h1, a1);
        accz = (__uint_as_float(l0) + __uint_as_float(h0))
             + (__uint_as_float(l1) + __uint_as_float(h1));
    }

    const float LLOG2PI = 117.62413f;  // 64 * log(2*pi)
    float em = -0.5f*accy - 0.5f*(__ldg(&g_lvsum[k]) + accz + LLOG2PI);

    float m = em;
    #pragma unroll
    for (int off = 8; off; off >>= 1)
        m = fmaxf(m, __shfl_xor_sync(FULL, m, off));

    float emp = em - m;
    float E = __expf(fmaxf(emp, -80.f));

    int sample = s0 + si;
    g_E[sample*KK + k]   = E;
    g_emp[sample*KK + k] = emp;
    if (k == 0) g_rowmax[sample] = m;
}

// ---------------------------------------------------------------------------
// Phase 1: per-chunk (16 steps) matrix product, packed-f32x2 matmul.
// Lane (i = lane>>1, half h = lane&1) owns R[i][h*8 .. h*8+7].
// ---------------------------------------------------------------------------
__global__ void __launch_bounds__(32) phase1_kernel() {
    int c = blockIdx.x;
    int lane = threadIdx.x;
    int b = c / NC, cl = c % NC;
    int i = lane >> 1, h = lane & 1;

    // A columns packed: a2[j][p] = (A[j][h*8+2p], A[j][h*8+2p+1])
    u64t a2[KK][4];
    #pragma unroll
    for (int j = 0; j < KK; j++) {
        const ulonglong2* pa = (const ulonglong2*)(g_A + j*KK + h*8);
        ulonglong2 v0 = __ldg(pa), v1 = __ldg(pa + 1);
        a2[j][0] = v0.x; a2[j][1] = v0.y;
        a2[j][2] = v1.x; a2[j][3] = v1.y;
    }

    float R[8];
    #pragma unroll
    for (int kk = 0; kk < 8; kk++)
        R[kk] = (i == h*8 + kk) ? 1.f : 0.f;

    float rowlog = 0.f, rmsum = 0.f;

    int t0 = b*SS + cl*CH;
    int us = (cl == 0) ? 1 : 0;
    const float* prm = g_rowmax + t0;

    // E packed prefetch
    u64t Ep[4], Enp[4];
    {
        const ulonglong2* p4 = (const ulonglong2*)(g_E + (size_t)(t0 + us)*KK + h*8);
        ulonglong2 q0 = __ldg(p4), q1 = __ldg(p4 + 1);
        Ep[0]=q0.x; Ep[1]=q0.y; Ep[2]=q1.x; Ep[3]=q1.y;
    }
    float rmc = __ldg(prm + us), rmn = 0.f;

    #pragma unroll
    for (int u = 0; u < CH; u++) {
        if (u < us) continue;
        if (u + 1 < CH) {
            const ulonglong2* p4 = (const ulonglong2*)(g_E + (size_t)(t0 + u + 1)*KK + h*8);
            ulonglong2 q0 = __ldg(p4), q1 = __ldg(p4 + 1);
            Enp[0]=q0.x; Enp[1]=q0.y; Enp[2]=q1.x; Enp[3]=q1.y;
            rmn = __ldg(prm + u + 1);
        }
        rmsum += rmc;

        // gather full row i of R (own 8 + partner 8)
        float rp[8];
        #pragma unroll
        for (int j = 0; j < 8; j++) rp[j] = __shfl_xor_sync(FULL, R[j], 1);
        float ar[16];
        #pragma unroll
        for (int j = 0; j < 8; j++) {
            ar[j]   = h ? rp[j] : R[j];
            ar[j+8] = h ? R[j]  : rp[j];
        }

        u64t nw4[4] = {0ull, 0ull, 0ull, 0ull};
        #pragma unroll
        for (int j = 0; j < KK; j++) {
            u64t ajp; PK2(ajp, __float_as_uint(ar[j]), __float_as_uint(ar[j]));
            FMA2(nw4[0], ajp, a2[j][0], nw4[0]);
            FMA2(nw4[1], ajp, a2[j][1], nw4[1]);
            FMA2(nw4[2], ajp, a2[j][2], nw4[2]);
            FMA2(nw4[3], ajp, a2[j][3], nw4[3]);
        }
        #pragma unroll
        for (int p = 0; p < 4; p++) {
            MUL2(nw4[p], nw4[p], Ep[p]);
            unsigned lo, hi; UPK2(lo, hi, nw4[p]);
            R[2*p]   = __uint_as_float(lo);
            R[2*p+1] = __uint_as_float(hi);
        }

        if (((u + 1) & 7) == 0) {
            float mx = R[0];
            #pragma unroll
            for (int kk = 1; kk < 8; kk++) mx = fmaxf(mx, R[kk]);
            mx = fmaxf(mx, __shfl_xor_sync(FULL, mx, 1));
            mx = fmaxf(mx, 1e-37f);
            float inv = __fdividef(1.f, mx);
            #pragma unroll
            for (int kk = 0; kk < 8; kk++) R[kk] *= inv;
            rowlog += __logf(mx);
        }

        #pragma unroll
        for (int p = 0; p < 4; p++) Ep[p] = Enp[p];
        rmc = rmn;
    }

    #pragma unroll
    for (int kk = 0; kk < 8; kk++)
        g_Rn[c][i*KK + h*8 + kk] = R[kk];
    if (h == 0) g_rowlog[c][i] = rowlog;
    if (lane == 0) g_rmsum[c] = rmsum;
}

// ---------------------------------------------------------------------------
// Phase 2: one 256-thread block per batch (R8/R11 verbatim — proven)
// ---------------------------------------------------------------------------
__global__ void __launch_bounds__(256) phase2_kernel(const float* __restrict__ start_logits) {
    extern __shared__ __align__(16) float sm2[];
    float* Rs   = sm2;                 // [NC][256]
    float* rls  = Rs + NC*256;         // [NC][16]
    float* rms  = rls + NC*16;         // [NC]
    float* Ss   = rms + NC;            // [NSUP][256]
    float* srcv = Ss + NSUP*256;       // [NSUP]
    float* qs   = srcv + NSUP;         // [NSUP][16]
    float* Cs   = qs + NSUP*16;        // [NSUP]

    int b = blockIdx.x;
    int tid = threadIdx.x;
    int w = tid >> 5, lane = tid & 31;
    int kk = lane & 15;

    {
        const float4* src = (const float4*)(&g_Rn[b*NC][0]);
        float4* dst = (float4*)Rs;
        for (int i = tid; i < NC*64; i += 256) dst[i] = __ldg(src + i);
        const float4* s2 = (const float4*)(&g_rowlog[b*NC][0]);
        float4* d2 = (float4*)rls;
        for (int i = tid; i < NC*4; i += 256) d2[i] = __ldg(s2 + i);
        if (tid < NC) rms[tid] = __ldg(&g_rmsum[b*NC + tid]);
    }
    __syncthreads();

    int iRow = lane >> 1, h = lane & 1;

    #pragma unroll
    for (int ss2 = 0; ss2 < 2; ss2++) {
        int s = w + ss2*8;
        int c0 = s*SUPW;

        float acc[8];
        {
            const float4* p = (const float4*)(Rs + c0*256 + iRow*16 + h*8);
            float4 r0 = p[0], r1 = p[1];
            acc[0]=r0.x; acc[1]=r0.y; acc[2]=r0.z; acc[3]=r0.w;
            acc[4]=r1.x; acc[5]=r1.y; acc[6]=r1.z; acc[7]=r1.w;
        }
        float rlA = rls[c0*16 + iRow];

        for (int m = 1; m < SUPW; m++) {
            int cm = c0 + m;
            float rl = (lane < 16) ? rls[cm*16 + lane] : -3.4e38f;
            float rlmax = rl;
            #pragma unroll
            for (int off = 16; off; off >>= 1)
                rlmax = fmaxf(rlmax, __shfl_xor_sync(FULL, rlmax, off));
            float sB = __expf(rl - rlmax);

            float rp[8];
            #pragma unroll
            for (int j = 0; j < 8; j++) rp[j] = __shfl_xor_sync(FULL, acc[j], 1);
            float ar[16];
            #pragma unroll
            for (int j = 0; j < 8; j++) {
                ar[j]   = h ? rp[j]  : acc[j];
                ar[j+8] = h ? acc[j] : rp[j];
            }

            float nw[8];
            #pragma unroll
            for (int kk2 = 0; kk2 < 8; kk2++) nw[kk2] = 0.f;
            #pragma unroll
            for (int j = 0; j < 16; j++) {
                const float4* pb = (const float4*)(Rs + cm*256 + j*16 + h*8);
                float4 b0 = pb[0], b1 = pb[1];
                float aj = ar[j] * __shfl_sync(FULL, sB, j);
                nw[0] = fmaf(aj, b0.x, nw[0]);
                nw[1] = fmaf(aj, b0.y, nw[1]);
                nw[2] = fmaf(aj, b0.z, nw[2]);
                nw[3] = fmaf(aj, b0.w, nw[3]);
                nw[4] = fmaf(aj, b1.x, nw[4]);
                nw[5] = fmaf(aj, b1.y, nw[5]);
                nw[6] = fmaf(aj, b1.z, nw[6]);
                nw[7] = fmaf(aj, b1.w, nw[7]);
            }
            float mx = nw[0];
            #pragma unroll
            for (int kk2 = 1; kk2 < 8; kk2++) mx = fmaxf(mx, nw[kk2]);
            mx = fmaxf(mx, __shfl_xor_sync(FULL, mx, 1));
            mx = fmaxf(mx, 1e-37f);
            float inv = __fdividef(1.f, mx);
            #pragma unroll
            for (int kk2 = 0; kk2 < 8; kk2++) acc[kk2] = nw[kk2] * inv;
            rlA += rlmax + __logf(mx);
        }

        float srlmax = rlA;
        #pragma unroll
        for (int off = 16; off; off >>= 1)
            srlmax = fmaxf(srlmax, __shfl_xor_sync(FULL, srlmax, off));
        float rsc = __expf(rlA - srlmax);
        #pragma unroll
        for (int kk2 = 0; kk2 < 8; kk2++)
            Ss[s*256 + iRow*16 + h*8 + kk2] = acc[kk2] * rsc;
        if (lane == 0) {
            float t = 0.f;
            #pragma unroll
            for (int m = 0; m < SUPW; m++) t += rms[c0 + m];
            srcv[s] = t + srlmax;
        }
    }
    __syncthreads();

    if (w == 0) {
        float sv = __ldg(start_logits + kk);
        float sm = sv;
        #pragma unroll
        for (int off = 8; off; off >>= 1) sm = fmaxf(sm, __shfl_xor_sync(FULL, sm, off));
        float se = __expf(sv - sm);
        #pragma unroll
        for (int off = 8; off; off >>= 1) se += __shfl_xor_sync(FULL, se, off);
        float lstart = sv - sm - __logf(se);

        float e0 = __ldg(&g_emp[(size_t)(b*SS)*KK + kk]);
        float t = lstart + e0;
        float m0 = t;
        #pragma unroll
        for (int off = 8; off; off >>= 1) m0 = fmaxf(m0, __shfl_xor_sync(FULL, m0, off));
        float q = __expf(t - m0);
        float C = __ldg(&g_rowmax[b*SS]) + m0;

        float Bc[16], Bn[16];
        #pragma unroll
        for (int i = 0; i < 16; i++) Bc[i] = Ss[i*16 + kk];

        for (int c = 0; c < NSUP; c++) {
            if (c > 0) {
                if (lane < 16) qs[c*16 + kk] = q;
                if (lane == 0) Cs[c] = C;
            }
            if (c + 1 < NSUP) {
                #pragma unroll
                for (int i = 0; i < 16; i++) Bn[i] = Ss[(c+1)*256 + i*16 + kk];
            }
            float s0 = 0.f, s1 = 0.f, s2 = 0.f, s3 = 0.f;
            #pragma unroll
            for (int j = 0; j < 16; j += 4) {
                s0 = fmaf(__shfl_sync(FULL, q, j + 0), Bc[j + 0], s0);
                s1 = fmaf(__shfl_sync(FULL, q, j + 1), Bc[j + 1], s1);
                s2 = fmaf(__shfl_sync(FULL, q, j + 2), Bc[j + 2], s2);
                s3 = fmaf(__shfl_sync(FULL, q, j + 3), Bc[j + 3], s3);
            }
            float v = (s0 + s1) + (s2 + s3);
            C += srcv[c];
            if ((c & 7) == 7) {
                float mv = v;
                #pragma unroll
                for (int off = 8; off; off >>= 1)
                    mv = fmaxf(mv, __shfl_xor_sync(FULL, mv, off));
                mv = fmaxf(mv, 1e-37f);
                q = __fdividef(v, mv);
                C += __logf(mv);
            } else {
                q = v;
            }
            #pragma unroll
            for (int i = 0; i < 16; i++) Bc[i] = Bn[i];
        }
    }
    __syncthreads();

    #pragma unroll
    for (int ss2 = 0; ss2 < 2; ss2++) {
        int s = w + ss2*8;
        float q, C;
        if (s == 0) {
            float sv = __ldg(start_logits + kk);
            float sm = sv;
            #pragma unroll
            for (int off = 8; off; off >>= 1) sm = fmaxf(sm, __shfl_xor_sync(FULL, sm, off));
            float se = __expf(sv - sm);
            #pragma unroll
            for (int off = 8; off; off >>= 1) se += __shfl_xor_sync(FULL, se, off);
            float lstart = sv - sm - __logf(se);
            float e0 = __ldg(&g_emp[(size_t)(b*SS)*KK + kk]);
            float t = lstart + e0;
            float m0 = t;
            #pragma unroll
            for (int off = 8; off; off >>= 1) m0 = fmaxf(m0, __shfl_xor_sync(FULL, m0, off));
            q = __expf(t - m0);
            C = __ldg(&g_rowmax[b*SS]) + m0;
        } else {
            q = qs[s*16 + kk];
            C = Cs[s];
        }

        for (int m = 0; m < SUPW; m++) {
            int cl = s*SUPW + m;
            int gc = b*NC + cl;
            if (cl > 0) {
                if (lane < 16) g_qb[gc][kk] = q;
                if (lane == 0) g_Cb[gc] = C;
            }
            if (m + 1 < SUPW) {
                float rl = (lane < 16) ? rls[cl*16 + lane] : -3.4e38f;
                float rlmax = rl;
                #pragma unroll
                for (int off = 16; off; off >>= 1)
                    rlmax = fmaxf(rlmax, __shfl_xor_sync(FULL, rlmax, off));
                float smy = __expf(rl - rlmax);
                float qsc = q * smy;

                float s0 = 0.f, s1 = 0.f, s2 = 0.f, s3 = 0.f;
                #pragma unroll
                for (int j = 0; j < 16; j += 4) {
                    s0 = fmaf(__shfl_sync(FULL, qsc, j + 0), Rs[cl*256 + (j+0)*16 + kk], s0);
                    s1 = fmaf(__shfl_sync(FULL, qsc, j + 1), Rs[cl*256 + (j+1)*16 + kk], s1);
                    s2 = fmaf(__shfl_sync(FULL, qsc, j + 2), Rs[cl*256 + (j+2)*16 + kk], s2);
                    s3 = fmaf(__shfl_sync(FULL, qsc, j + 3), Rs[cl*256 + (j+3)*16 + kk], s3);
                }
                float v = (s0 + s1) + (s2 + s3);
                float mv = v;
                #pragma unroll
                for (int off = 8; off; off >>= 1)
                    mv = fmaxf(mv, __shfl_xor_sync(FULL, mv, off));
                mv = fmaxf(mv, 1e-37f);
                q = __fdividef(v, mv);
                C += rms[cl] + rlmax + __logf(mv);
            }
        }
    }
}

// ---------------------------------------------------------------------------
// Phase 3: per-chunk vector recursion (E recomputed from emp)
// ---------------------------------------------------------------------------
__global__ void __launch_bounds__(32) phase3_kernel(
    const float* __restrict__ start_logits, float* __restrict__ out)
{
    int c = blockIdx.x;
    int lane = threadIdx.x;
    int b = c / NC, cl = c % NC;
    int kk = lane & 15;

    float acol[KK];
    #pragma unroll
    for (int j = 0; j < KK; j++) acol[j] = __ldg(&g_A[j*KK + kk]);

    const float* pP = g_emp + (size_t)(b*SS + cl*CH)*KK;
    const float* prm = g_rowmax + b*SS + cl*CH;
    float* ob = out + (size_t)(b*SS + cl*CH)*KK;

    float bufE[CH], bufP[CH], rm[CH];
    #pragma unroll
    for (int u = 0; u < CH; u++) {
        bufP[u] = __ldg(pP + u*KK + kk);
        rm[u]   = __ldg(prm + u);
        bufE[u] = __expf(fmaxf(bufP[u], -80.f));
    }

    float q, C;
    if (cl == 0) {
        float sv = __ldg(start_logits + kk);
        float sm = sv;
        #pragma unroll
        for (int off = 8; off; off >>= 1) sm = fmaxf(sm, __shfl_xor_sync(FULL, sm, off));
        float se = __expf(sv - sm);
        #pragma unroll
        for (int off = 8; off; off >>= 1) se += __shfl_xor_sync(FULL, se, off);
        float lstart = sv - sm - __logf(se);

        float a0 = lstart + bufP[0] + rm[0];
        if (lane < 16) ob[kk] = a0;
        q = __expf(fmaxf(lstart + bufP[0], -80.f));
        C = rm[0];
    } else {
        q = __ldg(&g_qb[c][kk]);
        C = __ldg(&g_Cb[c]);
    }

    #pragma unroll
    for (int u = 0; u < CH; u++) {
        if (cl == 0 && u == 0) continue;
        float s0 = 0.f, s1 = 0.f, s2 = 0.f, s3 = 0.f;
        #pragma unroll
        for (int j = 0; j < KK; j += 4) {
            s0 = fmaf(__shfl_sync(FULL, q, j + 0), acol[j + 0], s0);
            s1 = fmaf(__shfl_sync(FULL, q, j + 1), acol[j + 1], s1);
            s2 = fmaf(__shfl_sync(FULL, q, j + 2), acol[j + 2], s2);
            s3 = fmaf(__shfl_sync(FULL, q, j + 3), acol[j + 3], s3);
        }
        float ssum = (s0 + s1) + (s2 + s3);
        ssum = fmaxf(ssum, 1e-37f);
        float ov = C + rm[u] + bufP[u] + __logf(ssum);
        if (lane < 16) ob[u*KK + kk] = ov;
        q = ssum * bufE[u];
        C += rm[u];
    }
}

// ---------------------------------------------------------------------------
extern "C" void kernel_launch(void* const* d_in, const int* in_sizes, int n_in,
                              void* d_out, int out_size) {
    const float* y   = (const float*)d_in[0];
    const float* z   = (const float*)d_in[1];
    const float* st  = (const float*)d_in[2];
    const float* tr  = (const float*)d_in[3];
    const float* mu  = (const float*)d_in[4];
    const float* lv  = (const float*)d_in[5];
    const float* wz  = (const float*)d_in[6];
    const float* ws  = (const float*)d_in[7];
    const float* bd  = (const float*)d_in[8];
    float* out = (float*)d_out;

    int p2_smem = (NC*256 + NC*16 + NC + NSUP*256 + NSUP + NSUP*16 + NSUP) * sizeof(float);
    cudaFuncSetAttribute(phase2_kernel,
                         cudaFuncAttributeMaxDynamicSharedMemorySize, p2_smem);

    setup_kernel<<<KK, 32>>>(lv, ws, tr, mu);
    emissions_kernel<<<NS/SPB, TPB>>>(y, z, wz, ws, bd);
    phase1_kernel<<<TOTCH, 32>>>();
    phase2_kernel<<<BB, 256, p2_smem>>>(st);
    phase3_kernel<<<TOTCH, 32>>>(st, out);
}

// round 14
// speedup vs baseline: 2.0704x; 1.2352x over previous
#include <cuda_runtime.h>

#define BB 16
#define SS 2048
#define KK 16
#define LL 64
#define II 256
#define NS (BB*SS)        // 32768
#define CH 16
#define NC (SS/CH)        // 128 chunks per batch
#define TOTCH (BB*NC)     // 2048
#define SUPW 8
#define NSUP (NC/SUPW)    // 16

#define SPB 32            // emissions samples per block (decoupled from CH)
#define TPB 256

#define FULL 0xffffffffu

// ---- packed f32x2 helpers ----
typedef unsigned long long u64t;
#define FMA2(d,a,b,c) asm volatile("fma.rn.f32x2 %0, %1, %2, %3;" : "=l"(d) : "l"(a), "l"(b), "l"(c))
#define ADD2(d,a,b)   asm volatile("add.rn.f32x2 %0, %1, %2;" : "=l"(d) : "l"(a), "l"(b))
#define MUL2(d,a,b)   asm volatile("mul.rn.f32x2 %0, %1, %2;" : "=l"(d) : "l"(a), "l"(b))
#define PK2(d,lo,hi)  asm volatile("mov.b64 %0, {%1, %2};" : "=l"(d) : "r"(lo), "r"(hi))
#define UPK2(lo,hi,s) asm volatile("mov.b64 {%0, %1}, %2;" : "=r"(lo), "=r"(hi) : "l"(s))
#define LDS2(a,b,addr) asm volatile("ld.shared.v2.u64 {%0, %1}, [%2];" : "=l"(a), "=l"(b) : "r"(addr))

__device__ __forceinline__ unsigned s2u(const void* p) {
    unsigned r;
    asm("{ .reg .u64 t; cvta.to.shared.u64 t, %1; cvt.u32.u64 %0, t; }" : "=r"(r) : "l"(p));
    return r;
}

// Scratch (device globals; no allocation allowed)
__device__ __align__(16) float g_E[NS*KK];
__device__ __align__(16) float g_emp[NS*KK];
__device__ __align__(16) float g_rowmax[NS];
__device__ __align__(16) float g_invvar[KK*LL];
__device__ __align__(16) float g_nm[KK*LL];           // -mu
__device__ float g_lvsum[KK];
__device__ float g_ws2[KK];
__device__ __align__(16) float g_A[KK*KK];
__device__ __align__(16) float g_Rn[TOTCH][KK*KK];
__device__ __align__(16) float g_rowlog[TOTCH][KK];
__device__ __align__(16) float g_rmsum[TOTCH];
__device__ float g_qb[TOTCH][KK];
__device__ float g_Cb[TOTCH];

// emissions dynamic smem layout (floats, all offsets 16B-aligned)
#define EM_ZA    0                        // z_a [64][32]        2048 f
#define EM_ZB    (EM_ZA + LL*SPB)         // z_b [32][68]        2176 f
#define EM_D     (EM_ZB + SPB*(LL+4))     // d   [32][256]       8192 f
#define EM_WS    (EM_D + SPB*II)          // ws  [16][260]       4160 f
#define EM_TOTAL (EM_WS + KK*(II+4))      // 16576 f = 66304 B

// ---------------------------------------------------------------------------
// Setup: one warp-block per state k. (R12 verbatim)
// ---------------------------------------------------------------------------
__global__ void __launch_bounds__(32) setup_kernel(
    const float* __restrict__ prior_logvar,
    const float* __restrict__ Ws,
    const float* __restrict__ trans,
    const float* __restrict__ mu)
{
    int w = blockIdx.x;
    int lane = threadIdx.x;

    float s = 0.f;
    #pragma unroll
    for (int e = 0; e < 2; e++) {
        int idx = w*LL + lane + 32*e;
        float lv = __ldg(prior_logvar + idx);
        g_invvar[idx] = 1.0f / (expf(lv) + 1e-8f);
        g_nm[idx] = -__ldg(mu + idx);
        s += lv;
    }
    #pragma unroll
    for (int off = 16; off; off >>= 1) s += __shfl_xor_sync(FULL, s, off);
    if (lane == 0) g_lvsum[w] = s;

    float s2 = 0.f;
    #pragma unroll
    for (int e = 0; e < 8; e++) {
        float v = __ldg(Ws + w*II + lane + 32*e);
        s2 = fmaf(v, v, s2);
    }
    #pragma unroll
    for (int off = 16; off; off >>= 1) s2 += __shfl_xor_sync(FULL, s2, off);
    if (lane == 0) g_ws2[w] = s2;

    float v = (lane < 16) ? __ldg(trans + w*KK + (lane & 15)) : -1e30f;
    float mx = v;
    #pragma unroll
    for (int off = 8; off; off >>= 1) mx = fmaxf(mx, __shfl_xor_sync(FULL, mx, off));
    float ex = (lane < 16) ? expf(v - mx) : 0.f;
    float se = ex;
    #pragma unroll
    for (int off = 8; off; off >>= 1) se += __shfl_xor_sync(FULL, se, off);
    if (lane < 16) g_A[w*KK + lane] = expf(v - mx - logf(se));
}

// ---------------------------------------------------------------------------
// Emissions: SPB=32 tile (dynamic smem); phase B handles 2 samples per thread
// ---------------------------------------------------------------------------
__global__ void __launch_bounds__(TPB, 3) emissions_kernel(
    const float* __restrict__ Y, const float* __restrict__ Z,
    const float* __restrict__ Wz, const float* __restrict__ Ws,
    const float* __restrict__ bdec)
{
    extern __shared__ __align__(16) float smE[];
    float* z_a  = smE + EM_ZA;    // [l][s]  stride SPB
    float* z_b  = smE + EM_ZB;    // [s][l]  stride LL+4
    float* d_sh = smE + EM_D;     // [s][i]  stride II
    float* ws_sh= smE + EM_WS;    // [k][i]  stride II+4

    int tid = threadIdx.x;
    int s0 = blockIdx.x * SPB;

    #pragma unroll
    for (int e = 0; e < (SPB*LL)/TPB; e++) {
        int idx = tid + TPB*e;
        int s = idx >> 6, l = idx & 63;
        float v = Z[(s0 + s)*LL + l];
        z_a[l*SPB + s] = v;
        z_b[s*(LL+4) + l] = v;
    }
    #pragma unroll
    for (int e = 0; e < (KK*II)/TPB; e++) {
        int idx = tid + TPB*e;
        ws_sh[(idx >> 8)*(II+4) + (idx & 255)] = Ws[idx];
    }
    __syncthreads();

    // ---- Phase A: base = b_dec + z @ Wz for 32 samples (16 packed pairs) ----
    {
        u64t bp[16];
        float bd = __ldg(bdec + tid);
        u64t bdp; PK2(bdp, __float_as_uint(bd), __float_as_uint(bd));
        #pragma unroll
        for (int p = 0; p < 16; p++) bp[p] = bdp;

        unsigned za0 = s2u(z_a);
        #pragma unroll 2
        for (int l = 0; l < LL; l++) {
            float wz = __ldg(Wz + l*II + tid);
            u64t wzp; PK2(wzp, __float_as_uint(wz), __float_as_uint(wz));
            unsigned row = za0 + l*(SPB*4);
            // group 0: samples 0..7
            {
                u64t z0,z1,z2,z3;
                LDS2(z0, z1, row);
                LDS2(z2, z3, row + 16);
                FMA2(bp[0], z0, wzp, bp[0]);
                FMA2(bp[1], z1, wzp, bp[1]);
                FMA2(bp[2], z2, wzp, bp[2]);
                FMA2(bp[3], z3, wzp, bp[3]);
            }
            // group 1: samples 8..15
            {
                u64t z0,z1,z2,z3;
                LDS2(z0, z1, row + 32);
                LDS2(z2, z3, row + 48);
                FMA2(bp[4], z0, wzp, bp[4]);
                FMA2(bp[5], z1, wzp, bp[5]);
                FMA2(bp[6], z2, wzp, bp[6]);
                FMA2(bp[7], z3, wzp, bp[7]);
            }
            // group 2: samples 16..23
            {
                u64t z0,z1,z2,z3;
                LDS2(z0, z1, row + 64);
                LDS2(z2, z3, row + 80);
                FMA2(bp[8],  z0, wzp, bp[8]);
                FMA2(bp[9],  z1, wzp, bp[9]);
                FMA2(bp[10], z2, wzp, bp[10]);
                FMA2(bp[11], z3, wzp, bp[11]);
            }
            // group 3: samples 24..31
            {
                u64t z0,z1,z2,z3;
                LDS2(z0, z1, row + 96);
                LDS2(z2, z3, row + 112);
                FMA2(bp[12], z0, wzp, bp[12]);
                FMA2(bp[13], z1, wzp, bp[13]);
                FMA2(bp[14], z2, wzp, bp[14]);
                FMA2(bp[15], z3, wzp, bp[15]);
            }
        }
        #pragma unroll
        for (int p = 0; p < 16; p++) {
            unsigned u0, u1; UPK2(u0, u1, bp[p]);
            int s = 2*p;
            float y0 = __ldg(Y + (size_t)(s0 + s)*II + tid);
            float y1 = __ldg(Y + (size_t)(s0 + s + 1)*II + tid);
            d_sh[s*II + tid]       = y0 - __uint_as_float(u0);
            d_sh[(s + 1)*II + tid] = y1 - __uint_as_float(u1);
        }
    }
    __syncthreads();

    // ---- Phase B: thread (si, k) handles samples sa=si and sb=si+16 ----
    int si = tid >> 4;
    int k  = tid & 15;
    int sa = si, sb = si + 16;

    // ||d||^2 for both samples (cooperative over k-lanes)
    float sda = 0.f, sdb = 0.f;
    #pragma unroll
    for (int t = 0; t < 16; t++) {
        float va = d_sh[sa*II + t*16 + k];
        float vb = d_sh[sb*II + t*16 + k];
        sda = fmaf(va, va, sda);
        sdb = fmaf(vb, vb, sdb);
    }
    #pragma unroll
    for (int off = 8; off; off >>= 1) {
        sda += __shfl_xor_sync(FULL, sda, off);
        sdb += __shfl_xor_sync(FULL, sdb, off);
    }

    // dot(d, Ws_k) for both samples: ws row loaded once
    float dota, dotb;
    {
        unsigned dra = s2u(&d_sh[sa*II]);
        unsigned drb = s2u(&d_sh[sb*II]);
        unsigned wrow = s2u(&ws_sh[k*(II+4)]);
        u64t a0 = 0ull, a1 = 0ull, b0 = 0ull, b1 = 0ull;
        #pragma unroll 8
        for (int i = 0; i < II/4; i++) {
            u64t x0, x1, y0, y1, w0, w1;
            LDS2(x0, x1, dra + i*16);
            LDS2(y0, y1, drb + i*16);
            LDS2(w0, w1, wrow + i*16);
            FMA2(a0, x0, w0, a0);
            FMA2(a1, x1, w1, a1);
            FMA2(b0, y0, w0, b0);
            FMA2(b1, y1, w1, b1);
        }
        unsigned l0, h0, l1, h1;
        UPK2(l0, h0, a0); UPK2(l1, h1, a1);
        dota = (__uint_as_float(l0) + __uint_as_float(h0))
             + (__uint_as_float(l1) + __uint_as_float(h1));
        UPK2(l0, h0, b0); UPK2(l1, h1, b1);
        dotb = (__uint_as_float(l0) + __uint_as_float(h0))
             + (__uint_as_float(l1) + __uint_as_float(h1));
    }
    float ws2k = __ldg(&g_ws2[k]);
    float accya = sda - 2.f*dota + ws2k;
    float accyb = sdb - 2.f*dotb + ws2k;

    // z-prior quadratic for both samples: nm/iv loaded once
    float accza, acczb;
    {
        unsigned zra = s2u(&z_b[sa*(LL+4)]);
        unsigned zrb = s2u(&z_b[sb*(LL+4)]);
        const ulonglong2* nm2 = (const ulonglong2*)(g_nm + k*LL);
        const ulonglong2* iv2 = (const ulonglong2*)(g_invvar + k*LL);
        u64t a0 = 0ull, a1 = 0ull, b0 = 0ull, b1 = 0ull;
        #pragma unroll
        for (int i = 0; i < LL/4; i++) {
            u64t za0v, za1v, zb0v, zb1v;
            LDS2(za0v, za1v, zra + i*16);
            LDS2(zb0v, zb1v, zrb + i*16);
            ulonglong2 mv = __ldg(nm2 + i);
            ulonglong2 vv = __ldg(iv2 + i);
            u64t t0, t1;
            ADD2(t0, za0v, mv.x);
            ADD2(t1, za1v, mv.y);
            MUL2(t0, t0, t0);
            MUL2(t1, t1, t1);
            FMA2(a0, t0, vv.x, a0);
            FMA2(a1, t1, vv.y, a1);
            ADD2(t0, zb0v, mv.x);
            ADD2(t1, zb1v, mv.y);
            MUL2(t0, t0, t0);
            MUL2(t1, t1, t1);
            FMA2(b0, t0, vv.x, b0);
            FMA2(b1, t1, vv.y, b1);
        }
        unsigned l0, h0, l1, h1;
        UPK2(l0, h0, a0); UPK2(l1, h1, a1);
        accza = (__uint_as_float(l0) + __uint_as_float(h0))
              + (__uint_as_float(l1) + __uint_as_float(h1));
        UPK2(l0, h0, b0); UPK2(l1, h1, b1);
        acczb = (__uint_as_float(l0) + __uint_as_float(h0))
              + (__uint_as_float(l1) + __uint_as_float(h1));
    }

    const float LLOG2PI = 117.62413f;  // 64 * log(2*pi)
    float lvs = __ldg(&g_lvsum[k]);
    float ema = -0.5f*accya - 0.5f*(lvs + accza + LLOG2PI);
    float emb = -0.5f*accyb - 0.5f*(lvs + acczb + LLOG2PI);

    float ma = ema, mb = emb;
    #pragma unroll
    for (int off = 8; off; off >>= 1) {
        ma = fmaxf(ma, __shfl_xor_sync(FULL, ma, off));
        mb = fmaxf(mb, __shfl_xor_sync(FULL, mb, off));
    }

    float empa = ema - ma;
    float empb = emb - mb;
    float Ea = __expf(fmaxf(empa, -80.f));
    float Eb = __expf(fmaxf(empb, -80.f));

    int sampa = s0 + sa, sampb = s0 + sb;
    g_E[sampa*KK + k]   = Ea;
    g_emp[sampa*KK + k] = empa;
    g_E[sampb*KK + k]   = Eb;
    g_emp[sampb*KK + k] = empb;
    if (k == 0) {
        g_rowmax[sampa] = ma;
        g_rowmax[sampb] = mb;
    }
}

// ---------------------------------------------------------------------------
// Phase 1: per-chunk (16 steps) matrix product, packed-f32x2 (R12 verbatim)
// ---------------------------------------------------------------------------
__global__ void __launch_bounds__(32) phase1_kernel() {
    int c = blockIdx.x;
    int lane = threadIdx.x;
    int b = c / NC, cl = c % NC;
    int i = lane >> 1, h = lane & 1;

    u64t a2[KK][4];
    #pragma unroll
    for (int j = 0; j < KK; j++) {
        const ulonglong2* pa = (const ulonglong2*)(g_A + j*KK + h*8);
        ulonglong2 v0 = __ldg(pa), v1 = __ldg(pa + 1);
        a2[j][0] = v0.x; a2[j][1] = v0.y;
        a2[j][2] = v1.x; a2[j][3] = v1.y;
    }

    float R[8];
    #pragma unroll
    for (int kk = 0; kk < 8; kk++)
        R[kk] = (i == h*8 + kk) ? 1.f : 0.f;

    float rowlog = 0.f, rmsum = 0.f;

    int t0 = b*SS + cl*CH;
    int us = (cl == 0) ? 1 : 0;
    const float* prm = g_rowmax + t0;

    u64t Ep[4], Enp[4];
    {
        const ulonglong2* p4 = (const ulonglong2*)(g_E + (size_t)(t0 + us)*KK + h*8);
        ulonglong2 q0 = __ldg(p4), q1 = __ldg(p4 + 1);
        Ep[0]=q0.x; Ep[1]=q0.y; Ep[2]=q1.x; Ep[3]=q1.y;
    }
    float rmc = __ldg(prm + us), rmn = 0.f;

    #pragma unroll
    for (int u = 0; u < CH; u++) {
        if (u < us) continue;
        if (u + 1 < CH) {
            const ulonglong2* p4 = (const ulonglong2*)(g_E + (size_t)(t0 + u + 1)*KK + h*8);
            ulonglong2 q0 = __ldg(p4), q1 = __ldg(p4 + 1);
            Enp[0]=q0.x; Enp[1]=q0.y; Enp[2]=q1.x; Enp[3]=q1.y;
            rmn = __ldg(prm + u + 1);
        }
        rmsum += rmc;

        float rp[8];
        #pragma unroll
        for (int j = 0; j < 8; j++) rp[j] = __shfl_xor_sync(FULL, R[j], 1);
        float ar[16];
        #pragma unroll
        for (int j = 0; j < 8; j++) {
            ar[j]   = h ? rp[j] : R[j];
            ar[j+8] = h ? R[j]  : rp[j];
        }

        u64t nw4[4] = {0ull, 0ull, 0ull, 0ull};
        #pragma unroll
        for (int j = 0; j < KK; j++) {
            u64t ajp; PK2(ajp, __float_as_uint(ar[j]), __float_as_uint(ar[j]));
            FMA2(nw4[0], ajp, a2[j][0], nw4[0]);
            FMA2(nw4[1], ajp, a2[j][1], nw4[1]);
            FMA2(nw4[2], ajp, a2[j][2], nw4[2]);
            FMA2(nw4[3], ajp, a2[j][3], nw4[3]);
        }
        #pragma unroll
        for (int p = 0; p < 4; p++) {
            MUL2(nw4[p], nw4[p], Ep[p]);
            unsigned lo, hi; UPK2(lo, hi, nw4[p]);
            R[2*p]   = __uint_as_float(lo);
            R[2*p+1] = __uint_as_float(hi);
        }

        if (((u + 1) & 7) == 0) {
            float mx = R[0];
            #pragma unroll
            for (int kk = 1; kk < 8; kk++) mx = fmaxf(mx, R[kk]);
            mx = fmaxf(mx, __shfl_xor_sync(FULL, mx, 1));
            mx = fmaxf(mx, 1e-37f);
            float inv = __fdividef(1.f, mx);
            #pragma unroll
            for (int kk = 0; kk < 8; kk++) R[kk] *= inv;
            rowlog += __logf(mx);
        }

        #pragma unroll
        for (int p = 0; p < 4; p++) Ep[p] = Enp[p];
        rmc = rmn;
    }

    #pragma unroll
    for (int kk = 0; kk < 8; kk++)
        g_Rn[c][i*KK + h*8 + kk] = R[kk];
    if (h == 0) g_rowlog[c][i] = rowlog;
    if (lane == 0) g_rmsum[c] = rmsum;
}

// ---------------------------------------------------------------------------
// Phase 2: one 256-thread block per batch (R12 verbatim — proven)
// ---------------------------------------------------------------------------
__global__ void __launch_bounds__(256) phase2_kernel(const float* __restrict__ start_logits) {
    extern __shared__ __align__(16) float sm2[];
    float* Rs   = sm2;                 // [NC][256]
    float* rls  = Rs + NC*256;         // [NC][16]
    float* rms  = rls + NC*16;         // [NC]
    float* Ss   = rms + NC;            // [NSUP][256]
    float* srcv = Ss + NSUP*256;       // [NSUP]
    float* qs   = srcv + NSUP;         // [NSUP][16]
    float* Cs   = qs + NSUP*16;        // [NSUP]

    int b = blockIdx.x;
    int tid = threadIdx.x;
    int w = tid >> 5, lane = tid & 31;
    int kk = lane & 15;

    {
        const float4* src = (const float4*)(&g_Rn[b*NC][0]);
        float4* dst = (float4*)Rs;
        for (int i = tid; i < NC*64; i += 256) dst[i] = __ldg(src + i);
        const float4* s2 = (const float4*)(&g_rowlog[b*NC][0]);
        float4* d2 = (float4*)rls;
        for (int i = tid; i < NC*4; i += 256) d2[i] = __ldg(s2 + i);
        if (tid < NC) rms[tid] = __ldg(&g_rmsum[b*NC + tid]);
    }
    __syncthreads();

    int iRow = lane >> 1, h = lane & 1;

    #pragma unroll
    for (int ss2 = 0; ss2 < 2; ss2++) {
        int s = w + ss2*8;
        int c0 = s*SUPW;

        float acc[8];
        {
            const float4* p = (const float4*)(Rs + c0*256 + iRow*16 + h*8);
            float4 r0 = p[0], r1 = p[1];
            acc[0]=r0.x; acc[1]=r0.y; acc[2]=r0.z; acc[3]=r0.w;
            acc[4]=r1.x; acc[5]=r1.y; acc[6]=r1.z; acc[7]=r1.w;
        }
        float rlA = rls[c0*16 + iRow];

        for (int m = 1; m < SUPW; m++) {
            int cm = c0 + m;
            float rl = (lane < 16) ? rls[cm*16 + lane] : -3.4e38f;
            float rlmax = rl;
            #pragma unroll
            for (int off = 16; off; off >>= 1)
                rlmax = fmaxf(rlmax, __shfl_xor_sync(FULL, rlmax, off));
            float sB = __expf(rl - rlmax);

            float rp[8];
            #pragma unroll
            for (int j = 0; j < 8; j++) rp[j] = __shfl_xor_sync(FULL, acc[j], 1);
            float ar[16];
            #pragma unroll
            for (int j = 0; j < 8; j++) {
                ar[j]   = h ? rp[j]  : acc[j];
                ar[j+8] = h ? acc[j] : rp[j];
            }

            float nw[8];
            #pragma unroll
            for (int kk2 = 0; kk2 < 8; kk2++) nw[kk2] = 0.f;
            #pragma unroll
            for (int j = 0; j < 16; j++) {
                const float4* pb = (const float4*)(Rs + cm*256 + j*16 + h*8);
                float4 b0 = pb[0], b1 = pb[1];
                float aj = ar[j] * __shfl_sync(FULL, sB, j);
                nw[0] = fmaf(aj, b0.x, nw[0]);
                nw[1] = fmaf(aj, b0.y, nw[1]);
                nw[2] = fmaf(aj, b0.z, nw[2]);
                nw[3] = fmaf(aj, b0.w, nw[3]);
                nw[4] = fmaf(aj, b1.x, nw[4]);
                nw[5] = fmaf(aj, b1.y, nw[5]);
                nw[6] = fmaf(aj, b1.z, nw[6]);
                nw[7] = fmaf(aj, b1.w, nw[7]);
            }
            float mx = nw[0];
            #pragma unroll
            for (int kk2 = 1; kk2 < 8; kk2++) mx = fmaxf(mx, nw[kk2]);
            mx = fmaxf(mx, __shfl_xor_sync(FULL, mx, 1));
            mx = fmaxf(mx, 1e-37f);
            float inv = __fdividef(1.f, mx);
            #pragma unroll
            for (int kk2 = 0; kk2 < 8; kk2++) acc[kk2] = nw[kk2] * inv;
            rlA += rlmax + __logf(mx);
        }

        float srlmax = rlA;
        #pragma unroll
        for (int off = 16; off; off >>= 1)
            srlmax = fmaxf(srlmax, __shfl_xor_sync(FULL, srlmax, off));
        float rsc = __expf(rlA - srlmax);
        #pragma unroll
        for (int kk2 = 0; kk2 < 8; kk2++)
            Ss[s*256 + iRow*16 + h*8 + kk2] = acc[kk2] * rsc;
        if (lane == 0) {
            float t = 0.f;
            #pragma unroll
            for (int m = 0; m < SUPW; m++) t += rms[c0 + m];
            srcv[s] = t + srlmax;
        }
    }
    __syncthreads();

    if (w == 0) {
        float sv = __ldg(start_logits + kk);
        float sm = sv;
        #pragma unroll
        for (int off = 8; off; off >>= 1) sm = fmaxf(sm, __shfl_xor_sync(FULL, sm, off));
        float se = __expf(sv - sm);
        #pragma unroll
        for (int off = 8; off; off >>= 1) se += __shfl_xor_sync(FULL, se, off);
        float lstart = sv - sm - __logf(se);

        float e0 = __ldg(&g_emp[(size_t)(b*SS)*KK + kk]);
        float t = lstart + e0;
        float m0 = t;
        #pragma unroll
        for (int off = 8; off; off >>= 1) m0 = fmaxf(m0, __shfl_xor_sync(FULL, m0, off));
        float q = __expf(t - m0);
        float C = __ldg(&g_rowmax[b*SS]) + m0;

        float Bc[16], Bn[16];
        #pragma unroll
        for (int i = 0; i < 16; i++) Bc[i] = Ss[i*16 + kk];

        for (int c = 0; c < NSUP; c++) {
            if (c > 0) {
                if (lane < 16) qs[c*16 + kk] = q;
                if (lane == 0) Cs[c] = C;
            }
            if (c + 1 < NSUP) {
                #pragma unroll
                for (int i = 0; i < 16; i++) Bn[i] = Ss[(c+1)*256 + i*16 + kk];
            }
            float s0 = 0.f, s1 = 0.f, s2 = 0.f, s3 = 0.f;
            #pragma unroll
            for (int j = 0; j < 16; j += 4) {
                s0 = fmaf(__shfl_sync(FULL, q, j + 0), Bc[j + 0], s0);
                s1 = fmaf(__shfl_sync(FULL, q, j + 1), Bc[j + 1], s1);
                s2 = fmaf(__shfl_sync(FULL, q, j + 2), Bc[j + 2], s2);
                s3 = fmaf(__shfl_sync(FULL, q, j + 3), Bc[j + 3], s3);
            }
            float v = (s0 + s1) + (s2 + s3);
            C += srcv[c];
            if ((c & 7) == 7) {
                float mv = v;
                #pragma unroll
                for (int off = 8; off; off >>= 1)
                    mv = fmaxf(mv, __shfl_xor_sync(FULL, mv, off));
                mv = fmaxf(mv, 1e-37f);
                q = __fdividef(v, mv);
                C += __logf(mv);
            } else {
                q = v;
            }
            #pragma unroll
            for (int i = 0; i < 16; i++) Bc[i] = Bn[i];
        }
    }
    __syncthreads();

    #pragma unroll
    for (int ss2 = 0; ss2 < 2; ss2++) {
        int s = w + ss2*8;
        float q, C;
        if (s == 0) {
            float sv = __ldg(start_logits + kk);
            float sm = sv;
            #pragma unroll
            for (int off = 8; off; off >>= 1) sm = fmaxf(sm, __shfl_xor_sync(FULL, sm, off));
            float se = __expf(sv - sm);
            #pragma unroll
            for (int off = 8; off; off >>= 1) se += __shfl_xor_sync(FULL, se, off);
            float lstart = sv - sm - __logf(se);
            float e0 = __ldg(&g_emp[(size_t)(b*SS)*KK + kk]);
            float t = lstart + e0;
            float m0 = t;
            #pragma unroll
            for (int off = 8; off; off >>= 1) m0 = fmaxf(m0, __shfl_xor_sync(FULL, m0, off));
            q = __expf(t - m0);
            C = __ldg(&g_rowmax[b*SS]) + m0;
        } else {
            q = qs[s*16 + kk];
            C = Cs[s];
        }

        for (int m = 0; m < SUPW; m++) {
            int cl = s*SUPW + m;
            int gc = b*NC + cl;
            if (cl > 0) {
                if (lane < 16) g_qb[gc][kk] = q;
                if (lane == 0) g_Cb[gc] = C;
            }
            if (m + 1 < SUPW) {
                float rl = (lane < 16) ? rls[cl*16 + lane] : -3.4e38f;
                float rlmax = rl;
                #pragma unroll
                for (int off = 16; off; off >>= 1)
                    rlmax = fmaxf(rlmax, __shfl_xor_sync(FULL, rlmax, off));
                float smy = __expf(rl - rlmax);
                float qsc = q * smy;

                float s0 = 0.f, s1 = 0.f, s2 = 0.f, s3 = 0.f;
                #pragma unroll
                for (int j = 0; j < 16; j += 4) {
                    s0 = fmaf(__shfl_sync(FULL, qsc, j + 0), Rs[cl*256 + (j+0)*16 + kk], s0);
                    s1 = fmaf(__shfl_sync(FULL, qsc, j + 1), Rs[cl*256 + (j+1)*16 + kk], s1);
                    s2 = fmaf(__shfl_sync(FULL, qsc, j + 2), Rs[cl*256 + (j+2)*16 + kk], s2);
                    s3 = fmaf(__shfl_sync(FULL, qsc, j + 3), Rs[cl*256 + (j+3)*16 + kk], s3);
                }
                float v = (s0 + s1) + (s2 + s3);
                float mv = v;
                #pragma unroll
                for (int off = 8; off; off >>= 1)
                    mv = fmaxf(mv, __shfl_xor_sync(FULL, mv, off));
                mv = fmaxf(mv, 1e-37f);
                q = __fdividef(v, mv);
                C += rms[cl] + rlmax + __logf(mv);
            }
        }
    }
}

// ---------------------------------------------------------------------------
// Phase 3: per-chunk vector recursion (R12 verbatim)
// ---------------------------------------------------------------------------
__global__ void __launch_bounds__(32) phase3_kernel(
    const float* __restrict__ start_logits, float* __restrict__ out)
{
    int c = blockIdx.x;
    int lane = threadIdx.x;
    int b = c / NC, cl = c % NC;
    int kk = lane & 15;

    float acol[KK];
    #pragma unroll
    for (int j = 0; j < KK; j++) acol[j] = __ldg(&g_A[j*KK + kk]);

    const float* pP = g_emp + (size_t)(b*SS + cl*CH)*KK;
    const float* prm = g_rowmax + b*SS + cl*CH;
    float* ob = out + (size_t)(b*SS + cl*CH)*KK;

    float bufE[CH], bufP[CH], rm[CH];
    #pragma unroll
    for (int u = 0; u < CH; u++) {
        bufP[u] = __ldg(pP + u*KK + kk);
        rm[u]   = __ldg(prm + u);
        bufE[u] = __expf(fmaxf(bufP[u], -80.f));
    }

    float q, C;
    if (cl == 0) {
        float sv = __ldg(start_logits + kk);
        float sm = sv;
        #pragma unroll
        for (int off = 8; off; off >>= 1) sm = fmaxf(sm, __shfl_xor_sync(FULL, sm, off));
        float se = __expf(sv - sm);
        #pragma unroll
        for (int off = 8; off; off >>= 1) se += __shfl_xor_sync(FULL, se, off);
        float lstart = sv - sm - __logf(se);

        float a0 = lstart + bufP[0] + rm[0];
        if (lane < 16) ob[kk] = a0;
        q = __expf(fmaxf(lstart + bufP[0], -80.f));
        C = rm[0];
    } else {
        q = __ldg(&g_qb[c][kk]);
        C = __ldg(&g_Cb[c]);
    }

    #pragma unroll
    for (int u = 0; u < CH; u++) {
        if (cl == 0 && u == 0) continue;
        float s0 = 0.f, s1 = 0.f, s2 = 0.f, s3 = 0.f;
        #pragma unroll
        for (int j = 0; j < KK; j += 4) {
            s0 = fmaf(__shfl_sync(FULL, q, j + 0), acol[j + 0], s0);
            s1 = fmaf(__shfl_sync(FULL, q, j + 1), acol[j + 1], s1);
            s2 = fmaf(__shfl_sync(FULL, q, j + 2), acol[j + 2], s2);
            s3 = fmaf(__shfl_sync(FULL, q, j + 3), acol[j + 3], s3);
        }
        float ssum = (s0 + s1) + (s2 + s3);
        ssum = fmaxf(ssum, 1e-37f);
        float ov = C + rm[u] + bufP[u] + __logf(ssum);
        if (lane < 16) ob[u*KK + kk] = ov;
        q = ssum * bufE[u];
        C += rm[u];
    }
}

// ---------------------------------------------------------------------------
extern "C" void kernel_launch(void* const* d_in, const int* in_sizes, int n_in,
                              void* d_out, int out_size) {
    const float* y   = (const float*)d_in[0];
    const float* z   = (const float*)d_in[1];
    const float* st  = (const float*)d_in[2];
    const float* tr  = (const float*)d_in[3];
    const float* mu  = (const float*)d_in[4];
    const float* lv  = (const float*)d_in[5];
    const float* wz  = (const float*)d_in[6];
    const float* ws  = (const float*)d_in[7];
    const float* bd  = (const float*)d_in[8];
    float* out = (float*)d_out;

    int em_smem = EM_TOTAL * sizeof(float);   // ~66.3 KB (dynamic)
    int p2_smem = (NC*256 + NC*16 + NC + NSUP*256 + NSUP + NSUP*16 + NSUP) * sizeof(float);
    cudaFuncSetAttribute(emissions_kernel,
                         cudaFuncAttributeMaxDynamicSharedMemorySize, em_smem);
    cudaFuncSetAttribute(phase2_kernel,
                         cudaFuncAttributeMaxDynamicSharedMemorySize, p2_smem);

    setup_kernel<<<KK, 32>>>(lv, ws, tr, mu);
    emissions_kernel<<<NS/SPB, TPB, em_smem>>>(y, z, wz, ws, bd);
    phase1_kernel<<<TOTCH, 32>>>();
    phase2_kernel<<<BB, 256, p2_smem>>>(st);
    phase3_kernel<<<TOTCH, 32>>>(st, out);
}

// round 15
// speedup vs baseline: 2.1094x; 1.0188x over previous
#include <cuda_runtime.h>

#define BB 16
#define SS 2048
#define KK 16
#define LL 64
#define II 256
#define NS (BB*SS)        // 32768
#define CH 16
#define NC (SS/CH)        // 128 chunks per batch
#define TOTCH (BB*NC)     // 2048
#define SUPW 8
#define NSUP (NC/SUPW)    // 16

#define SPB 32            // emissions samples per block (decoupled from CH)
#define TPB 256
#define TPB2 1024         // phase2 threads (32 warps for staging MLP)

#define FULL 0xffffffffu

// ---- packed f32x2 helpers ----
typedef unsigned long long u64t;
#define FMA2(d,a,b,c) asm volatile("fma.rn.f32x2 %0, %1, %2, %3;" : "=l"(d) : "l"(a), "l"(b), "l"(c))
#define ADD2(d,a,b)   asm volatile("add.rn.f32x2 %0, %1, %2;" : "=l"(d) : "l"(a), "l"(b))
#define MUL2(d,a,b)   asm volatile("mul.rn.f32x2 %0, %1, %2;" : "=l"(d) : "l"(a), "l"(b))
#define PK2(d,lo,hi)  asm volatile("mov.b64 %0, {%1, %2};" : "=l"(d) : "r"(lo), "r"(hi))
#define UPK2(lo,hi,s) asm volatile("mov.b64 {%0, %1}, %2;" : "=r"(lo), "=r"(hi) : "l"(s))
#define LDS2(a,b,addr) asm volatile("ld.shared.v2.u64 {%0, %1}, [%2];" : "=l"(a), "=l"(b) : "r"(addr))

__device__ __forceinline__ unsigned s2u(const void* p) {
    unsigned r;
    asm("{ .reg .u64 t; cvta.to.shared.u64 t, %1; cvt.u32.u64 %0, t; }" : "=r"(r) : "l"(p));
    return r;
}

// Scratch (device globals; no allocation allowed)
__device__ __align__(16) float g_E[NS*KK];
__device__ __align__(16) float g_emp[NS*KK];
__device__ __align__(16) float g_rowmax[NS];
__device__ __align__(16) float g_invvar[KK*LL];
__device__ __align__(16) float g_nm[KK*LL];           // -mu
__device__ float g_lvsum[KK];
__device__ float g_ws2[KK];
__device__ __align__(16) float g_A[KK*KK];
__device__ __align__(16) float g_Rn[TOTCH][KK*KK];
__device__ __align__(16) float g_rowlog[TOTCH][KK];
__device__ __align__(16) float g_rmsum[TOTCH];
__device__ float g_qb[TOTCH][KK];
__device__ float g_Cb[TOTCH];

// emissions dynamic smem layout (floats, all offsets 16B-aligned)
#define EM_ZA    0                        // z_a [64][32]        2048 f
#define EM_ZB    (EM_ZA + LL*SPB)         // z_b [32][68]        2176 f
#define EM_D     (EM_ZB + SPB*(LL+4))     // d   [32][256]       8192 f
#define EM_WS    (EM_D + SPB*II)          // ws  [16][260]       4160 f
#define EM_TOTAL (EM_WS + KK*(II+4))      // 16576 f = 66304 B

// ---------------------------------------------------------------------------
// Setup: one warp-block per state k. (R12 verbatim)
// ---------------------------------------------------------------------------
__global__ void __launch_bounds__(32) setup_kernel(
    const float* __restrict__ prior_logvar,
    const float* __restrict__ Ws,
    const float* __restrict__ trans,
    const float* __restrict__ mu)
{
    int w = blockIdx.x;
    int lane = threadIdx.x;

    float s = 0.f;
    #pragma unroll
    for (int e = 0; e < 2; e++) {
        int idx = w*LL + lane + 32*e;
        float lv = __ldg(prior_logvar + idx);
        g_invvar[idx] = 1.0f / (expf(lv) + 1e-8f);
        g_nm[idx] = -__ldg(mu + idx);
        s += lv;
    }
    #pragma unroll
    for (int off = 16; off; off >>= 1) s += __shfl_xor_sync(FULL, s, off);
    if (lane == 0) g_lvsum[w] = s;

    float s2 = 0.f;
    #pragma unroll
    for (int e = 0; e < 8; e++) {
        float v = __ldg(Ws + w*II + lane + 32*e);
        s2 = fmaf(v, v, s2);
    }
    #pragma unroll
    for (int off = 16; off; off >>= 1) s2 += __shfl_xor_sync(FULL, s2, off);
    if (lane == 0) g_ws2[w] = s2;

    float v = (lane < 16) ? __ldg(trans + w*KK + (lane & 15)) : -1e30f;
    float mx = v;
    #pragma unroll
    for (int off = 8; off; off >>= 1) mx = fmaxf(mx, __shfl_xor_sync(FULL, mx, off));
    float ex = (lane < 16) ? expf(v - mx) : 0.f;
    float se = ex;
    #pragma unroll
    for (int off = 8; off; off >>= 1) se += __shfl_xor_sync(FULL, se, off);
    if (lane < 16) g_A[w*KK + lane] = expf(v - mx - logf(se));
}

// ---------------------------------------------------------------------------
// Emissions: SPB=32 tile (dynamic smem); phase B handles 2 samples per thread
// ---------------------------------------------------------------------------
__global__ void __launch_bounds__(TPB, 3) emissions_kernel(
    const float* __restrict__ Y, const float* __restrict__ Z,
    const float* __restrict__ Wz, const float* __restrict__ Ws,
    const float* __restrict__ bdec)
{
    extern __shared__ __align__(16) float smE[];
    float* z_a  = smE + EM_ZA;    // [l][s]  stride SPB
    float* z_b  = smE + EM_ZB;    // [s][l]  stride LL+4
    float* d_sh = smE + EM_D;     // [s][i]  stride II
    float* ws_sh= smE + EM_WS;    // [k][i]  stride II+4

    int tid = threadIdx.x;
    int s0 = blockIdx.x * SPB;

    #pragma unroll
    for (int e = 0; e < (SPB*LL)/TPB; e++) {
        int idx = tid + TPB*e;
        int s = idx >> 6, l = idx & 63;
        float v = Z[(s0 + s)*LL + l];
        z_a[l*SPB + s] = v;
        z_b[s*(LL+4) + l] = v;
    }
    #pragma unroll
    for (int e = 0; e < (KK*II)/TPB; e++) {
        int idx = tid + TPB*e;
        ws_sh[(idx >> 8)*(II+4) + (idx & 255)] = Ws[idx];
    }
    __syncthreads();

    // ---- Phase A: base = b_dec + z @ Wz for 32 samples (16 packed pairs) ----
    {
        u64t bp[16];
        float bd = __ldg(bdec + tid);
        u64t bdp; PK2(bdp, __float_as_uint(bd), __float_as_uint(bd));
        #pragma unroll
        for (int p = 0; p < 16; p++) bp[p] = bdp;

        unsigned za0 = s2u(z_a);
        #pragma unroll 4
        for (int l = 0; l < LL; l++) {
            float wz = __ldg(Wz + l*II + tid);
            u64t wzp; PK2(wzp, __float_as_uint(wz), __float_as_uint(wz));
            unsigned row = za0 + l*(SPB*4);
            // group 0: samples 0..7
            {
                u64t z0,z1,z2,z3;
                LDS2(z0, z1, row);
                LDS2(z2, z3, row + 16);
                FMA2(bp[0], z0, wzp, bp[0]);
                FMA2(bp[1], z1, wzp, bp[1]);
                FMA2(bp[2], z2, wzp, bp[2]);
                FMA2(bp[3], z3, wzp, bp[3]);
            }
            // group 1: samples 8..15
            {
                u64t z0,z1,z2,z3;
                LDS2(z0, z1, row + 32);
                LDS2(z2, z3, row + 48);
                FMA2(bp[4], z0, wzp, bp[4]);
                FMA2(bp[5], z1, wzp, bp[5]);
                FMA2(bp[6], z2, wzp, bp[6]);
                FMA2(bp[7], z3, wzp, bp[7]);
            }
            // group 2: samples 16..23
            {
                u64t z0,z1,z2,z3;
                LDS2(z0, z1, row + 64);
                LDS2(z2, z3, row + 80);
                FMA2(bp[8],  z0, wzp, bp[8]);
                FMA2(bp[9],  z1, wzp, bp[9]);
                FMA2(bp[10], z2, wzp, bp[10]);
                FMA2(bp[11], z3, wzp, bp[11]);
            }
            // group 3: samples 24..31
            {
                u64t z0,z1,z2,z3;
                LDS2(z0, z1, row + 96);
                LDS2(z2, z3, row + 112);
                FMA2(bp[12], z0, wzp, bp[12]);
                FMA2(bp[13], z1, wzp, bp[13]);
                FMA2(bp[14], z2, wzp, bp[14]);
                FMA2(bp[15], z3, wzp, bp[15]);
            }
        }
        #pragma unroll
        for (int p = 0; p < 16; p++) {
            unsigned u0, u1; UPK2(u0, u1, bp[p]);
            int s = 2*p;
            float y0 = __ldg(Y + (size_t)(s0 + s)*II + tid);
            float y1 = __ldg(Y + (size_t)(s0 + s + 1)*II + tid);
            d_sh[s*II + tid]       = y0 - __uint_as_float(u0);
            d_sh[(s + 1)*II + tid] = y1 - __uint_as_float(u1);
        }
    }
    __syncthreads();

    // ---- Phase B: thread (si, k) handles samples sa=si and sb=si+16 ----
    int si = tid >> 4;
    int k  = tid & 15;
    int sa = si, sb = si + 16;

    float sda = 0.f, sdb = 0.f;
    #pragma unroll
    for (int t = 0; t < 16; t++) {
        float va = d_sh[sa*II + t*16 + k];
        float vb = d_sh[sb*II + t*16 + k];
        sda = fmaf(va, va, sda);
        sdb = fmaf(vb, vb, sdb);
    }
    #pragma unroll
    for (int off = 8; off; off >>= 1) {
        sda += __shfl_xor_sync(FULL, sda, off);
        sdb += __shfl_xor_sync(FULL, sdb, off);
    }

    float dota, dotb;
    {
        unsigned dra = s2u(&d_sh[sa*II]);
        unsigned drb = s2u(&d_sh[sb*II]);
        unsigned wrow = s2u(&ws_sh[k*(II+4)]);
        u64t a0 = 0ull, a1 = 0ull, b0 = 0ull, b1 = 0ull;
        #pragma unroll 8
        for (int i = 0; i < II/4; i++) {
            u64t x0, x1, y0, y1, w0, w1;
            LDS2(x0, x1, dra + i*16);
            LDS2(y0, y1, drb + i*16);
            LDS2(w0, w1, wrow + i*16);
            FMA2(a0, x0, w0, a0);
            FMA2(a1, x1, w1, a1);
            FMA2(b0, y0, w0, b0);
            FMA2(b1, y1, w1, b1);
        }
        unsigned l0, h0, l1, h1;
        UPK2(l0, h0, a0); UPK2(l1, h1, a1);
        dota = (__uint_as_float(l0) + __uint_as_float(h0))
             + (__uint_as_float(l1) + __uint_as_float(h1));
        UPK2(l0, h0, b0); UPK2(l1, h1, b1);
        dotb = (__uint_as_float(l0) + __uint_as_float(h0))
             + (__uint_as_float(l1) + __uint_as_float(h1));
    }
    float ws2k = __ldg(&g_ws2[k]);
    float accya = sda - 2.f*dota + ws2k;
    float accyb = sdb - 2.f*dotb + ws2k;

    float accza, acczb;
    {
        unsigned zra = s2u(&z_b[sa*(LL+4)]);
        unsigned zrb = s2u(&z_b[sb*(LL+4)]);
        const ulonglong2* nm2 = (const ulonglong2*)(g_nm + k*LL);
        const ulonglong2* iv2 = (const ulonglong2*)(g_invvar + k*LL);
        u64t a0 = 0ull, a1 = 0ull, b0 = 0ull, b1 = 0ull;
        #pragma unroll
        for (int i = 0; i < LL/4; i++) {
            u64t za0v, za1v, zb0v, zb1v;
            LDS2(za0v, za1v, zra + i*16);
            LDS2(zb0v, zb1v, zrb + i*16);
            ulonglong2 mv = __ldg(nm2 + i);
            ulonglong2 vv = __ldg(iv2 + i);
            u64t t0, t1;
            ADD2(t0, za0v, mv.x);
            ADD2(t1, za1v, mv.y);
            MUL2(t0, t0, t0);
            MUL2(t1, t1, t1);
            FMA2(a0, t0, vv.x, a0);
            FMA2(a1, t1, vv.y, a1);
            ADD2(t0, zb0v, mv.x);
            ADD2(t1, zb1v, mv.y);
            MUL2(t0, t0, t0);
            MUL2(t1, t1, t1);
            FMA2(b0, t0, vv.x, b0);
            FMA2(b1, t1, vv.y, b1);
        }
        unsigned l0, h0, l1, h1;
        UPK2(l0, h0, a0); UPK2(l1, h1, a1);
        accza = (__uint_as_float(l0) + __uint_as_float(h0))
              + (__uint_as_float(l1) + __uint_as_float(h1));
        UPK2(l0, h0, b0); UPK2(l1, h1, b1);
        acczb = (__uint_as_float(l0) + __uint_as_float(h0))
              + (__uint_as_float(l1) + __uint_as_float(h1));
    }

    const float LLOG2PI = 117.62413f;  // 64 * log(2*pi)
    float lvs = __ldg(&g_lvsum[k]);
    float ema = -0.5f*accya - 0.5f*(lvs + accza + LLOG2PI);
    float emb = -0.5f*accyb - 0.5f*(lvs + acczb + LLOG2PI);

    float ma = ema, mb = emb;
    #pragma unroll
    for (int off = 8; off; off >>= 1) {
        ma = fmaxf(ma, __shfl_xor_sync(FULL, ma, off));
        mb = fmaxf(mb, __shfl_xor_sync(FULL, mb, off));
    }

    float empa = ema - ma;
    float empb = emb - mb;
    float Ea = __expf(fmaxf(empa, -80.f));
    float Eb = __expf(fmaxf(empb, -80.f));

    int sampa = s0 + sa, sampb = s0 + sb;
    g_E[sampa*KK + k]   = Ea;
    g_emp[sampa*KK + k] = empa;
    g_E[sampb*KK + k]   = Eb;
    g_emp[sampb*KK + k] = empb;
    if (k == 0) {
        g_rowmax[sampa] = ma;
        g_rowmax[sampb] = mb;
    }
}

// ---------------------------------------------------------------------------
// Phase 1: per-chunk (16 steps) matrix product, packed-f32x2 (R12 verbatim)
// ---------------------------------------------------------------------------
__global__ void __launch_bounds__(32) phase1_kernel() {
    int c = blockIdx.x;
    int lane = threadIdx.x;
    int b = c / NC, cl = c % NC;
    int i = lane >> 1, h = lane & 1;

    u64t a2[KK][4];
    #pragma unroll
    for (int j = 0; j < KK; j++) {
        const ulonglong2* pa = (const ulonglong2*)(g_A + j*KK + h*8);
        ulonglong2 v0 = __ldg(pa), v1 = __ldg(pa + 1);
        a2[j][0] = v0.x; a2[j][1] = v0.y;
        a2[j][2] = v1.x; a2[j][3] = v1.y;
    }

    float R[8];
    #pragma unroll
    for (int kk = 0; kk < 8; kk++)
        R[kk] = (i == h*8 + kk) ? 1.f : 0.f;

    float rowlog = 0.f, rmsum = 0.f;

    int t0 = b*SS + cl*CH;
    int us = (cl == 0) ? 1 : 0;
    const float* prm = g_rowmax + t0;

    u64t Ep[4], Enp[4];
    {
        const ulonglong2* p4 = (const ulonglong2*)(g_E + (size_t)(t0 + us)*KK + h*8);
        ulonglong2 q0 = __ldg(p4), q1 = __ldg(p4 + 1);
        Ep[0]=q0.x; Ep[1]=q0.y; Ep[2]=q1.x; Ep[3]=q1.y;
    }
    float rmc = __ldg(prm + us), rmn = 0.f;

    #pragma unroll
    for (int u = 0; u < CH; u++) {
        if (u < us) continue;
        if (u + 1 < CH) {
            const ulonglong2* p4 = (const ulonglong2*)(g_E + (size_t)(t0 + u + 1)*KK + h*8);
            ulonglong2 q0 = __ldg(p4), q1 = __ldg(p4 + 1);
            Enp[0]=q0.x; Enp[1]=q0.y; Enp[2]=q1.x; Enp[3]=q1.y;
            rmn = __ldg(prm + u + 1);
        }
        rmsum += rmc;

        float rp[8];
        #pragma unroll
        for (int j = 0; j < 8; j++) rp[j] = __shfl_xor_sync(FULL, R[j], 1);
        float ar[16];
        #pragma unroll
        for (int j = 0; j < 8; j++) {
            ar[j]   = h ? rp[j] : R[j];
            ar[j+8] = h ? R[j]  : rp[j];
        }

        u64t nw4[4] = {0ull, 0ull, 0ull, 0ull};
        #pragma unroll
        for (int j = 0; j < KK; j++) {
            u64t ajp; PK2(ajp, __float_as_uint(ar[j]), __float_as_uint(ar[j]));
            FMA2(nw4[0], ajp, a2[j][0], nw4[0]);
            FMA2(nw4[1], ajp, a2[j][1], nw4[1]);
            FMA2(nw4[2], ajp, a2[j][2], nw4[2]);
            FMA2(nw4[3], ajp, a2[j][3], nw4[3]);
        }
        #pragma unroll
        for (int p = 0; p < 4; p++) {
            MUL2(nw4[p], nw4[p], Ep[p]);
            unsigned lo, hi; UPK2(lo, hi, nw4[p]);
            R[2*p]   = __uint_as_float(lo);
            R[2*p+1] = __uint_as_float(hi);
        }

        if (((u + 1) & 7) == 0) {
            float mx = R[0];
            #pragma unroll
            for (int kk = 1; kk < 8; kk++) mx = fmaxf(mx, R[kk]);
            mx = fmaxf(mx, __shfl_xor_sync(FULL, mx, 1));
            mx = fmaxf(mx, 1e-37f);
            float inv = __fdividef(1.f, mx);
            #pragma unroll
            for (int kk = 0; kk < 8; kk++) R[kk] *= inv;
            rowlog += __logf(mx);
        }

        #pragma unroll
        for (int p = 0; p < 4; p++) Ep[p] = Enp[p];
        rmc = rmn;
    }

    #pragma unroll
    for (int kk = 0; kk < 8; kk++)
        g_Rn[c][i*KK + h*8 + kk] = R[kk];
    if (h == 0) g_rowlog[c][i] = rowlog;
    if (lane == 0) g_rmsum[c] = rmsum;
}

// ---------------------------------------------------------------------------
// Phase 2: one 1024-thread block per batch. 32 warps stage (4x MLP);
// warps 0-15 build supers; warp 0 serial; warps 0-15 propagate.
// ---------------------------------------------------------------------------
__global__ void __launch_bounds__(TPB2) phase2_kernel(const float* __restrict__ start_logits) {
    extern __shared__ __align__(16) float sm2[];
    float* Rs   = sm2;                 // [NC][256]
    float* rls  = Rs + NC*256;         // [NC][16]
    float* rms  = rls + NC*16;         // [NC]
    float* Ss   = rms + NC;            // [NSUP][256]
    float* srcv = Ss + NSUP*256;       // [NSUP]
    float* qs   = srcv + NSUP;         // [NSUP][16]
    float* Cs   = qs + NSUP*16;        // [NSUP]

    int b = blockIdx.x;
    int tid = threadIdx.x;
    int w = tid >> 5, lane = tid & 31;
    int kk = lane & 15;

    // ---- staging: 32 warps of MLP ----
    {
        const float4* src = (const float4*)(&g_Rn[b*NC][0]);
        float4* dst = (float4*)Rs;
        for (int i = tid; i < NC*64; i += TPB2) dst[i] = __ldg(src + i);
        const float4* s2 = (const float4*)(&g_rowlog[b*NC][0]);
        float4* d2 = (float4*)rls;
        if (tid < NC*4) d2[tid] = __ldg(s2 + tid);
        if (tid < NC) rms[tid] = __ldg(&g_rmsum[b*NC + tid]);
    }
    __syncthreads();

    int iRow = lane >> 1, h = lane & 1;

    // ---- super-combine: warp w (w < 16) -> super w ----
    if (w < NSUP) {
        int s = w;
        int c0 = s*SUPW;

        float acc[8];
        {
            const float4* p = (const float4*)(Rs + c0*256 + iRow*16 + h*8);
            float4 r0 = p[0], r1 = p[1];
            acc[0]=r0.x; acc[1]=r0.y; acc[2]=r0.z; acc[3]=r0.w;
            acc[4]=r1.x; acc[5]=r1.y; acc[6]=r1.z; acc[7]=r1.w;
        }
        float rlA = rls[c0*16 + iRow];

        for (int m = 1; m < SUPW; m++) {
            int cm = c0 + m;
            float rl = (lane < 16) ? rls[cm*16 + lane] : -3.4e38f;
            float rlmax = rl;
            #pragma unroll
            for (int off = 16; off; off >>= 1)
                rlmax = fmaxf(rlmax, __shfl_xor_sync(FULL, rlmax, off));
            float sB = __expf(rl - rlmax);

            float rp[8];
            #pragma unroll
            for (int j = 0; j < 8; j++) rp[j] = __shfl_xor_sync(FULL, acc[j], 1);
            float ar[16];
            #pragma unroll
            for (int j = 0; j < 8; j++) {
                ar[j]   = h ? rp[j]  : acc[j];
                ar[j+8] = h ? acc[j] : rp[j];
            }

            float nw[8];
            #pragma unroll
            for (int kk2 = 0; kk2 < 8; kk2++) nw[kk2] = 0.f;
            #pragma unroll
            for (int j = 0; j < 16; j++) {
                const float4* pb = (const float4*)(Rs + cm*256 + j*16 + h*8);
                float4 b0 = pb[0], b1 = pb[1];
                float aj = ar[j] * __shfl_sync(FULL, sB, j);
                nw[0] = fmaf(aj, b0.x, nw[0]);
                nw[1] = fmaf(aj, b0.y, nw[1]);
                nw[2] = fmaf(aj, b0.z, nw[2]);
                nw[3] = fmaf(aj, b0.w, nw[3]);
                nw[4] = fmaf(aj, b1.x, nw[4]);
                nw[5] = fmaf(aj, b1.y, nw[5]);
                nw[6] = fmaf(aj, b1.z, nw[6]);
                nw[7] = fmaf(aj, b1.w, nw[7]);
            }
            float mx = nw[0];
            #pragma unroll
            for (int kk2 = 1; kk2 < 8; kk2++) mx = fmaxf(mx, nw[kk2]);
            mx = fmaxf(mx, __shfl_xor_sync(FULL, mx, 1));
            mx = fmaxf(mx, 1e-37f);
            float inv = __fdividef(1.f, mx);
            #pragma unroll
            for (int kk2 = 0; kk2 < 8; kk2++) acc[kk2] = nw[kk2] * inv;
            rlA += rlmax + __logf(mx);
        }

        float srlmax = rlA;
        #pragma unroll
        for (int off = 16; off; off >>= 1)
            srlmax = fmaxf(srlmax, __shfl_xor_sync(FULL, srlmax, off));
        float rsc = __expf(rlA - srlmax);
        #pragma unroll
        for (int kk2 = 0; kk2 < 8; kk2++)
            Ss[s*256 + iRow*16 + h*8 + kk2] = acc[kk2] * rsc;
        if (lane == 0) {
            float t = 0.f;
            #pragma unroll
            for (int m = 0; m < SUPW; m++) t += rms[c0 + m];
            srcv[s] = t + srlmax;
        }
    }
    __syncthreads();

    // ---- warp 0: serial combine over 16 supers ----
    if (w == 0) {
        float sv = __ldg(start_logits + kk);
        float sm = sv;
        #pragma unroll
        for (int off = 8; off; off >>= 1) sm = fmaxf(sm, __shfl_xor_sync(FULL, sm, off));
        float se = __expf(sv - sm);
        #pragma unroll
        for (int off = 8; off; off >>= 1) se += __shfl_xor_sync(FULL, se, off);
        float lstart = sv - sm - __logf(se);

        float e0 = __ldg(&g_emp[(size_t)(b*SS)*KK + kk]);
        float t = lstart + e0;
        float m0 = t;
        #pragma unroll
        for (int off = 8; off; off >>= 1) m0 = fmaxf(m0, __shfl_xor_sync(FULL, m0, off));
        float q = __expf(t - m0);
        float C = __ldg(&g_rowmax[b*SS]) + m0;

        float Bc[16], Bn[16];
        #pragma unroll
        for (int i = 0; i < 16; i++) Bc[i] = Ss[i*16 + kk];

        for (int c = 0; c < NSUP; c++) {
            if (c > 0) {
                if (lane < 16) qs[c*16 + kk] = q;
                if (lane == 0) Cs[c] = C;
            }
            if (c + 1 < NSUP) {
                #pragma unroll
                for (int i = 0; i < 16; i++) Bn[i] = Ss[(c+1)*256 + i*16 + kk];
            }
            float s0 = 0.f, s1 = 0.f, s2 = 0.f, s3 = 0.f;
            #pragma unroll
            for (int j = 0; j < 16; j += 4) {
                s0 = fmaf(__shfl_sync(FULL, q, j + 0), Bc[j + 0], s0);
                s1 = fmaf(__shfl_sync(FULL, q, j + 1), Bc[j + 1], s1);
                s2 = fmaf(__shfl_sync(FULL, q, j + 2), Bc[j + 2], s2);
                s3 = fmaf(__shfl_sync(FULL, q, j + 3), Bc[j + 3], s3);
            }
            float v = (s0 + s1) + (s2 + s3);
            C += srcv[c];
            if ((c & 7) == 7) {
                float mv = v;
                #pragma unroll
                for (int off = 8; off; off >>= 1)
                    mv = fmaxf(mv, __shfl_xor_sync(FULL, mv, off));
                mv = fmaxf(mv, 1e-37f);
                q = __fdividef(v, mv);
                C += __logf(mv);
            } else {
                q = v;
            }
            #pragma unroll
            for (int i = 0; i < 16; i++) Bc[i] = Bn[i];
        }
    }
    __syncthreads();

    // ---- propagate: warp w (w < 16) -> super w ----
    if (w < NSUP) {
        int s = w;
        float q, C;
        if (s == 0) {
            float sv = __ldg(start_logits + kk);
            float sm = sv;
            #pragma unroll
            for (int off = 8; off; off >>= 1) sm = fmaxf(sm, __shfl_xor_sync(FULL, sm, off));
            float se = __expf(sv - sm);
            #pragma unroll
            for (int off = 8; off; off >>= 1) se += __shfl_xor_sync(FULL, se, off);
            float lstart = sv - sm - __logf(se);
            float e0 = __ldg(&g_emp[(size_t)(b*SS)*KK + kk]);
            float t = lstart + e0;
            float m0 = t;
            #pragma unroll
            for (int off = 8; off; off >>= 1) m0 = fmaxf(m0, __shfl_xor_sync(FULL, m0, off));
            q = __expf(t - m0);
            C = __ldg(&g_rowmax[b*SS]) + m0;
        } else {
            q = qs[s*16 + kk];
            C = Cs[s];
        }

        for (int m = 0; m < SUPW; m++) {
            int cl = s*SUPW + m;
            int gc = b*NC + cl;
            if (cl > 0) {
                if (lane < 16) g_qb[gc][kk] = q;
                if (lane == 0) g_Cb[gc] = C;
            }
            if (m + 1 < SUPW) {
                float rl = (lane < 16) ? rls[cl*16 + lane] : -3.4e38f;
                float rlmax = rl;
                #pragma unroll
                for (int off = 16; off; off >>= 1)
                    rlmax = fmaxf(rlmax, __shfl_xor_sync(FULL, rlmax, off));
                float smy = __expf(rl - rlmax);
                float qsc = q * smy;

                float s0 = 0.f, s1 = 0.f, s2 = 0.f, s3 = 0.f;
                #pragma unroll
                for (int j = 0; j < 16; j += 4) {
                    s0 = fmaf(__shfl_sync(FULL, qsc, j + 0), Rs[cl*256 + (j+0)*16 + kk], s0);
                    s1 = fmaf(__shfl_sync(FULL, qsc, j + 1), Rs[cl*256 + (j+1)*16 + kk], s1);
                    s2 = fmaf(__shfl_sync(FULL, qsc, j + 2), Rs[cl*256 + (j+2)*16 + kk], s2);
                    s3 = fmaf(__shfl_sync(FULL, qsc, j + 3), Rs[cl*256 + (j+3)*16 + kk], s3);
                }
                float v = (s0 + s1) + (s2 + s3);
                float mv = v;
                #pragma unroll
                for (int off = 8; off; off >>= 1)
                    mv = fmaxf(mv, __shfl_xor_sync(FULL, mv, off));
                mv = fmaxf(mv, 1e-37f);
                q = __fdividef(v, mv);
                C += rms[cl] + rlmax + __logf(mv);
            }
        }
    }
}

// ---------------------------------------------------------------------------
// Phase 3: per-chunk vector recursion (R12 verbatim)
// ---------------------------------------------------------------------------
__global__ void __launch_bounds__(32) phase3_kernel(
    const float* __restrict__ start_logits, float* __restrict__ out)
{
    int c = blockIdx.x;
    int lane = threadIdx.x;
    int b = c / NC, cl = c % NC;
    int kk = lane & 15;

    float acol[KK];
    #pragma unroll
    for (int j = 0; j < KK; j++) acol[j] = __ldg(&g_A[j*KK + kk]);

    const float* pP = g_emp + (size_t)(b*SS + cl*CH)*KK;
    const float* prm = g_rowmax + b*SS + cl*CH;
    float* ob = out + (size_t)(b*SS + cl*CH)*KK;

    float bufE[CH], bufP[CH], rm[CH];
    #pragma unroll
    for (int u = 0; u < CH; u++) {
        bufP[u] = __ldg(pP + u*KK + kk);
        rm[u]   = __ldg(prm + u);
        bufE[u] = __expf(fmaxf(bufP[u], -80.f));
    }

    float q, C;
    if (cl == 0) {
        float sv = __ldg(start_logits + kk);
        float sm = sv;
        #pragma unroll
        for (int off = 8; off; off >>= 1) sm = fmaxf(sm, __shfl_xor_sync(FULL, sm, off));
        float se = __expf(sv - sm);
        #pragma unroll
        for (int off = 8; off; off >>= 1) se += __shfl_xor_sync(FULL, se, off);
        float lstart = sv - sm - __logf(se);

        float a0 = lstart + bufP[0] + rm[0];
        if (lane < 16) ob[kk] = a0;
        q = __expf(fmaxf(lstart + bufP[0], -80.f));
        C = rm[0];
    } else {
        q = __ldg(&g_qb[c][kk]);
        C = __ldg(&g_Cb[c]);
    }

    #pragma unroll
    for (int u = 0; u < CH; u++) {
        if (cl == 0 && u == 0) continue;
        float s0 = 0.f, s1 = 0.f, s2 = 0.f, s3 = 0.f;
        #pragma unroll
        for (int j = 0; j < KK; j += 4) {
            s0 = fmaf(__shfl_sync(FULL, q, j + 0), acol[j + 0], s0);
            s1 = fmaf(__shfl_sync(FULL, q, j + 1), acol[j + 1], s1);
            s2 = fmaf(__shfl_sync(FULL, q, j + 2), acol[j + 2], s2);
            s3 = fmaf(__shfl_sync(FULL, q, j + 3), acol[j + 3], s3);
        }
        float ssum = (s0 + s1) + (s2 + s3);
        ssum = fmaxf(ssum, 1e-37f);
        float ov = C + rm[u] + bufP[u] + __logf(ssum);
        if (lane < 16) ob[u*KK + kk] = ov;
        q = ssum * bufE[u];
        C += rm[u];
    }
}

// ---------------------------------------------------------------------------
extern "C" void kernel_launch(void* const* d_in, const int* in_sizes, int n_in,
                              void* d_out, int out_size) {
    const float* y   = (const float*)d_in[0];
    const float* z   = (const float*)d_in[1];
    const float* st  = (const float*)d_in[2];
    const float* tr  = (const float*)d_in[3];
    const float* mu  = (const float*)d_in[4];
    const float* lv  = (const float*)d_in[5];
    const float* wz  = (const float*)d_in[6];
    const float* ws  = (const float*)d_in[7];
    const float* bd  = (const float*)d_in[8];
    float* out = (float*)d_out;

    int em_smem = EM_TOTAL * sizeof(float);   // ~66.3 KB (dynamic)
    int p2_smem = (NC*256 + NC*16 + NC + NSUP*256 + NSUP + NSUP*16 + NSUP) * sizeof(float);
    cudaFuncSetAttribute(emissions_kernel,
                         cudaFuncAttributeMaxDynamicSharedMemorySize, em_smem);
    cudaFuncSetAttribute(phase2_kernel,
                         cudaFuncAttributeMaxDynamicSharedMemorySize, p2_smem);

    setup_kernel<<<KK, 32>>>(lv, ws, tr, mu);
    emissions_kernel<<<NS/SPB, TPB, em_smem>>>(y, z, wz, ws, bd);
    phase1_kernel<<<TOTCH, 32>>>();
    phase2_kernel<<<BB, TPB2, p2_smem>>>(st);
    phase3_kernel<<<TOTCH, 32>>>(st, out);
}

// round 17
// speedup vs baseline: 2.1409x; 1.0149x over previous
#include <cuda_runtime.h>

#define BB 16
#define SS 2048
#define KK 16
#define LL 64
#define II 256
#define NS (BB*SS)        // 32768
#define CH 16
#define NC (SS/CH)        // 128 chunks per batch
#define TOTCH (BB*NC)     // 2048
#define SUPW 8
#define NSUP (NC/SUPW)    // 16

#define SPB 32            // emissions samples per block (decoupled from CH)
#define TPB 256
#define TPB2 1024         // phase2 threads

#define FULL 0xffffffffu

// ---- packed f32x2 helpers ----
typedef unsigned long long u64t;
#define FMA2(d,a,b,c) asm volatile("fma.rn.f32x2 %0, %1, %2, %3;" : "=l"(d) : "l"(a), "l"(b), "l"(c))
#define ADD2(d,a,b)   asm volatile("add.rn.f32x2 %0, %1, %2;" : "=l"(d) : "l"(a), "l"(b))
#define MUL2(d,a,b)   asm volatile("mul.rn.f32x2 %0, %1, %2;" : "=l"(d) : "l"(a), "l"(b))
#define PK2(d,lo,hi)  asm volatile("mov.b64 %0, {%1, %2};" : "=l"(d) : "r"(lo), "r"(hi))
#define UPK2(lo,hi,s) asm volatile("mov.b64 {%0, %1}, %2;" : "=r"(lo), "=r"(hi) : "l"(s))
#define LDS2(a,b,addr) asm volatile("ld.shared.v2.u64 {%0, %1}, [%2];" : "=l"(a), "=l"(b) : "r"(addr))

__device__ __forceinline__ unsigned s2u(const void* p) {
    unsigned r;
    asm("{ .reg .u64 t; cvta.to.shared.u64 t, %1; cvt.u32.u64 %0, t; }" : "=r"(r) : "l"(p));
    return r;
}

// Scratch (device globals; no allocation allowed)
__device__ __align__(16) float g_E[NS*KK];
__device__ __align__(16) float g_emp[NS*KK];
__device__ __align__(16) float g_rowmax[NS];
__device__ __align__(16) float g_invvar[KK*LL];
__device__ __align__(16) float g_nm[KK*LL];           // -mu
__device__ float g_lvsum[KK];
__device__ float g_ws2[KK];
__device__ __align__(16) float g_A[KK*KK];
__device__ __align__(16) float g_Rn[TOTCH][KK*KK];    // chunk matrix, GLOBAL max = 1
__device__ __align__(16) float g_rc[TOTCH];           // scalar log-scale + rmsum
__device__ float g_qb[TOTCH][KK];
__device__ float g_Cb[TOTCH];

// emissions dynamic smem layout (floats, all offsets 16B-aligned)
#define EM_ZA    0                        // z_a [64][32]
#define EM_ZB    (EM_ZA + LL*SPB)         // z_b [32][68]
#define EM_D     (EM_ZB + SPB*(LL+4))     // d   [32][256]
#define EM_WS    (EM_D + SPB*II)          // ws  [16][260]
#define EM_TOTAL (EM_WS + KK*(II+4))      // 16576 f = 66304 B

// ---------------------------------------------------------------------------
// Setup: one warp-block per state k.
// ---------------------------------------------------------------------------
__global__ void __launch_bounds__(32) setup_kernel(
    const float* __restrict__ prior_logvar,
    const float* __restrict__ Ws,
    const float* __restrict__ trans,
    const float* __restrict__ mu)
{
    int w = blockIdx.x;
    int lane = threadIdx.x;

    float s = 0.f;
    #pragma unroll
    for (int e = 0; e < 2; e++) {
        int idx = w*LL + lane + 32*e;
        float lv = __ldg(prior_logvar + idx);
        g_invvar[idx] = 1.0f / (expf(lv) + 1e-8f);
        g_nm[idx] = -__ldg(mu + idx);
        s += lv;
    }
    #pragma unroll
    for (int off = 16; off; off >>= 1) s += __shfl_xor_sync(FULL, s, off);
    if (lane == 0) g_lvsum[w] = s;

    float s2 = 0.f;
    #pragma unroll
    for (int e = 0; e < 8; e++) {
        float v = __ldg(Ws + w*II + lane + 32*e);
        s2 = fmaf(v, v, s2);
    }
    #pragma unroll
    for (int off = 16; off; off >>= 1) s2 += __shfl_xor_sync(FULL, s2, off);
    if (lane == 0) g_ws2[w] = s2;

    float v = (lane < 16) ? __ldg(trans + w*KK + (lane & 15)) : -1e30f;
    float mx = v;
    #pragma unroll
    for (int off = 8; off; off >>= 1) mx = fmaxf(mx, __shfl_xor_sync(FULL, mx, off));
    float ex = (lane < 16) ? expf(v - mx) : 0.f;
    float se = ex;
    #pragma unroll
    for (int off = 8; off; off >>= 1) se += __shfl_xor_sync(FULL, se, off);
    if (lane < 16) g_A[w*KK + lane] = expf(v - mx - logf(se));
}

// ---------------------------------------------------------------------------
// Emissions: SPB=32 tile (dynamic smem); phase B handles 2 samples per thread
// ---------------------------------------------------------------------------
__global__ void __launch_bounds__(TPB, 3) emissions_kernel(
    const float* __restrict__ Y, const float* __restrict__ Z,
    const float* __restrict__ Wz, const float* __restrict__ Ws,
    const float* __restrict__ bdec)
{
    extern __shared__ __align__(16) float smE[];
    float* z_a  = smE + EM_ZA;
    float* z_b  = smE + EM_ZB;
    float* d_sh = smE + EM_D;
    float* ws_sh= smE + EM_WS;

    int tid = threadIdx.x;
    int s0 = blockIdx.x * SPB;

    #pragma unroll
    for (int e = 0; e < (SPB*LL)/TPB; e++) {
        int idx = tid + TPB*e;
        int s = idx >> 6, l = idx & 63;
        float v = Z[(s0 + s)*LL + l];
        z_a[l*SPB + s] = v;
        z_b[s*(LL+4) + l] = v;
    }
    #pragma unroll
    for (int e = 0; e < (KK*II)/TPB; e++) {
        int idx = tid + TPB*e;
        ws_sh[(idx >> 8)*(II+4) + (idx & 255)] = Ws[idx];
    }
    __syncthreads();

    {
        u64t bp[16];
        float bd = __ldg(bdec + tid);
        u64t bdp; PK2(bdp, __float_as_uint(bd), __float_as_uint(bd));
        #pragma unroll
        for (int p = 0; p < 16; p++) bp[p] = bdp;

        unsigned za0 = s2u(z_a);
        #pragma unroll 4
        for (int l = 0; l < LL; l++) {
            float wz = __ldg(Wz + l*II + tid);
            u64t wzp; PK2(wzp, __float_as_uint(wz), __float_as_uint(wz));
            unsigned row = za0 + l*(SPB*4);
            {
                u64t z0,z1,z2,z3;
                LDS2(z0, z1, row);
                LDS2(z2, z3, row + 16);
                FMA2(bp[0], z0, wzp, bp[0]);
                FMA2(bp[1], z1, wzp, bp[1]);
                FMA2(bp[2], z2, wzp, bp[2]);
                FMA2(bp[3], z3, wzp, bp[3]);
            }
            {
                u64t z0,z1,z2,z3;
                LDS2(z0, z1, row + 32);
                LDS2(z2, z3, row + 48);
                FMA2(bp[4], z0, wzp, bp[4]);
                FMA2(bp[5], z1, wzp, bp[5]);
                FMA2(bp[6], z2, wzp, bp[6]);
                FMA2(bp[7], z3, wzp, bp[7]);
            }
            {
                u64t z0,z1,z2,z3;
                LDS2(z0, z1, row + 64);
                LDS2(z2, z3, row + 80);
                FMA2(bp[8],  z0, wzp, bp[8]);
                FMA2(bp[9],  z1, wzp, bp[9]);
                FMA2(bp[10], z2, wzp, bp[10]);
                FMA2(bp[11], z3, wzp, bp[11]);
            }
            {
                u64t z0,z1,z2,z3;
                LDS2(z0, z1, row + 96);
                LDS2(z2, z3, row + 112);
                FMA2(bp[12], z0, wzp, bp[12]);
                FMA2(bp[13], z1, wzp, bp[13]);
                FMA2(bp[14], z2, wzp, bp[14]);
                FMA2(bp[15], z3, wzp, bp[15]);
            }
        }
        #pragma unroll
        for (int p = 0; p < 16; p++) {
            unsigned u0, u1; UPK2(u0, u1, bp[p]);
            int s = 2*p;
            float y0 = __ldg(Y + (size_t)(s0 + s)*II + tid);
            float y1 = __ldg(Y + (size_t)(s0 + s + 1)*II + tid);
            d_sh[s*II + tid]       = y0 - __uint_as_float(u0);
            d_sh[(s + 1)*II + tid] = y1 - __uint_as_float(u1);
        }
    }
    __syncthreads();

    int si = tid >> 4;
    int k  = tid & 15;
    int sa = si, sb = si + 16;

    float sda = 0.f, sdb = 0.f;
    #pragma unroll
    for (int t = 0; t < 16; t++) {
        float va = d_sh[sa*II + t*16 + k];
        float vb = d_sh[sb*II + t*16 + k];
        sda = fmaf(va, va, sda);
        sdb = fmaf(vb, vb, sdb);
    }
    #pragma unroll
    for (int off = 8; off; off >>= 1) {
        sda += __shfl_xor_sync(FULL, sda, off);
        sdb += __shfl_xor_sync(FULL, sdb, off);
    }

    float dota, dotb;
    {
        unsigned dra = s2u(&d_sh[sa*II]);
        unsigned drb = s2u(&d_sh[sb*II]);
        unsigned wrow = s2u(&ws_sh[k*(II+4)]);
        u64t a0 = 0ull, a1 = 0ull, b0 = 0ull, b1 = 0ull;
        #pragma unroll 8
        for (int i = 0; i < II/4; i++) {
            u64t x0, x1, y0, y1, w0, w1;
            LDS2(x0, x1, dra + i*16);
            LDS2(y0, y1, drb + i*16);
            LDS2(w0, w1, wrow + i*16);
            FMA2(a0, x0, w0, a0);
            FMA2(a1, x1, w1, a1);
            FMA2(b0, y0, w0, b0);
            FMA2(b1, y1, w1, b1);
        }
        unsigned l0, h0, l1, h1;
        UPK2(l0, h0, a0); UPK2(l1, h1, a1);
        dota = (__uint_as_float(l0) + __uint_as_float(h0))
             + (__uint_as_float(l1) + __uint_as_float(h1));
        UPK2(l0, h0, b0); UPK2(l1, h1, b1);
        dotb = (__uint_as_float(l0) + __uint_as_float(h0))
             + (__uint_as_float(l1) + __uint_as_float(h1));
    }
    float ws2k = __ldg(&g_ws2[k]);
    float accya = sda - 2.f*dota + ws2k;
    float accyb = sdb - 2.f*dotb + ws2k;

    float accza, acczb;
    {
        unsigned zra = s2u(&z_b[sa*(LL+4)]);
        unsigned zrb = s2u(&z_b[sb*(LL+4)]);
        const ulonglong2* nm2 = (const ulonglong2*)(g_nm + k*LL);
        const ulonglong2* iv2 = (const ulonglong2*)(g_invvar + k*LL);
        u64t a0 = 0ull, a1 = 0ull, b0 = 0ull, b1 = 0ull;
        #pragma unroll
        for (int i = 0; i < LL/4; i++) {
            u64t za0v, za1v, zb0v, zb1v;
            LDS2(za0v, za1v, zra + i*16);
            LDS2(zb0v, zb1v, zrb + i*16);
            ulonglong2 mv = __ldg(nm2 + i);
            ulonglong2 vv = __ldg(iv2 + i);
            u64t t0, t1;
            ADD2(t0, za0v, mv.x);
            ADD2(t1, za1v, mv.y);
            MUL2(t0, t0, t0);
            MUL2(t1, t1, t1);
            FMA2(a0, t0, vv.x, a0);
            FMA2(a1, t1, vv.y, a1);
            ADD2(t0, zb0v, mv.x);
            ADD2(t1, zb1v, mv.y);
            MUL2(t0, t0, t0);
            MUL2(t1, t1, t1);
            FMA2(b0, t0, vv.x, b0);
            FMA2(b1, t1, vv.y, b1);
        }
        unsigned l0, h0, l1, h1;
        UPK2(l0, h0, a0); UPK2(l1, h1, a1);
        accza = (__uint_as_float(l0) + __uint_as_float(h0))
              + (__uint_as_float(l1) + __uint_as_float(h1));
        UPK2(l0, h0, b0); UPK2(l1, h1, b1);
        acczb = (__uint_as_float(l0) + __uint_as_float(h0))
              + (__uint_as_float(l1) + __uint_as_float(h1));
    }

    const float LLOG2PI = 117.62413f;  // 64 * log(2*pi)
    float lvs = __ldg(&g_lvsum[k]);
    float ema = -0.5f*accya - 0.5f*(lvs + accza + LLOG2PI);
    float emb = -0.5f*accyb - 0.5f*(lvs + acczb + LLOG2PI);

    float ma = ema, mb = emb;
    #pragma unroll
    for (int off = 8; off; off >>= 1) {
        ma = fmaxf(ma, __shfl_xor_sync(FULL, ma, off));
        mb = fmaxf(mb, __shfl_xor_sync(FULL, mb, off));
    }

    float empa = ema - ma;
    float empb = emb - mb;
    float Ea = __expf(fmaxf(empa, -80.f));
    float Eb = __expf(fmaxf(empb, -80.f));

    int sampa = s0 + sa, sampb = s0 + sb;
    g_E[sampa*KK + k]   = Ea;
    g_emp[sampa*KK + k] = empa;
    g_E[sampb*KK + k]   = Eb;
    g_emp[sampb*KK + k] = empb;
    if (k == 0) {
        g_rowmax[sampa] = ma;
        g_rowmax[sampb] = mb;
    }
}

// ---------------------------------------------------------------------------
// Phase 1: per-chunk matrix product; epilogue folds per-row scales into the
// stored matrix (global max = 1) and emits ONE scalar g_rc per chunk.
// ---------------------------------------------------------------------------
__global__ void __launch_bounds__(32) phase1_kernel() {
    int c = blockIdx.x;
    int lane = threadIdx.x;
    int b = c / NC, cl = c % NC;
    int i = lane >> 1, h = lane & 1;

    u64t a2[KK][4];
    #pragma unroll
    for (int j = 0; j < KK; j++) {
        const ulonglong2* pa = (const ulonglong2*)(g_A + j*KK + h*8);
        ulonglong2 v0 = __ldg(pa), v1 = __ldg(pa + 1);
        a2[j][0] = v0.x; a2[j][1] = v0.y;
        a2[j][2] = v1.x; a2[j][3] = v1.y;
    }

    float R[8];
    #pragma unroll
    for (int kk = 0; kk < 8; kk++)
        R[kk] = (i == h*8 + kk) ? 1.f : 0.f;

    float rowlog = 0.f, rmsum = 0.f;

    int t0 = b*SS + cl*CH;
    int us = (cl == 0) ? 1 : 0;
    const float* prm = g_rowmax + t0;

    u64t Ep[4], Enp[4];
    {
        const ulonglong2* p4 = (const ulonglong2*)(g_E + (size_t)(t0 + us)*KK + h*8);
        ulonglong2 q0 = __ldg(p4), q1 = __ldg(p4 + 1);
        Ep[0]=q0.x; Ep[1]=q0.y; Ep[2]=q1.x; Ep[3]=q1.y;
    }
    float rmc = __ldg(prm + us), rmn = 0.f;

    #pragma unroll
    for (int u = 0; u < CH; u++) {
        if (u < us) continue;
        if (u + 1 < CH) {
            const ulonglong2* p4 = (const ulonglong2*)(g_E + (size_t)(t0 + u + 1)*KK + h*8);
            ulonglong2 q0 = __ldg(p4), q1 = __ldg(p4 + 1);
            Enp[0]=q0.x; Enp[1]=q0.y; Enp[2]=q1.x; Enp[3]=q1.y;
            rmn = __ldg(prm + u + 1);
        }
        rmsum += rmc;

        float rp[8];
        #pragma unroll
        for (int j = 0; j < 8; j++) rp[j] = __shfl_xor_sync(FULL, R[j], 1);
        float ar[16];
        #pragma unroll
        for (int j = 0; j < 8; j++) {
            ar[j]   = h ? rp[j] : R[j];
            ar[j+8] = h ? R[j]  : rp[j];
        }

        u64t nw4[4] = {0ull, 0ull, 0ull, 0ull};
        #pragma unroll
        for (int j = 0; j < KK; j++) {
            u64t ajp; PK2(ajp, __float_as_uint(ar[j]), __float_as_uint(ar[j]));
            FMA2(nw4[0], ajp, a2[j][0], nw4[0]);
            FMA2(nw4[1], ajp, a2[j][1], nw4[1]);
            FMA2(nw4[2], ajp, a2[j][2], nw4[2]);
            FMA2(nw4[3], ajp, a2[j][3], nw4[3]);
        }
        #pragma unroll
        for (int p = 0; p < 4; p++) {
            MUL2(nw4[p], nw4[p], Ep[p]);
            unsigned lo, hi; UPK2(lo, hi, nw4[p]);
            R[2*p]   = __uint_as_float(lo);
            R[2*p+1] = __uint_as_float(hi);
        }

        if (((u + 1) & 7) == 0) {
            float mx = R[0];
            #pragma unroll
            for (int kk = 1; kk < 8; kk++) mx = fmaxf(mx, R[kk]);
            mx = fmaxf(mx, __shfl_xor_sync(FULL, mx, 1));
            mx = fmaxf(mx, 1e-37f);
            float inv = __fdividef(1.f, mx);
            #pragma unroll
            for (int kk = 0; kk < 8; kk++) R[kk] *= inv;
            rowlog += __logf(mx);
        }

        #pragma unroll
        for (int p = 0; p < 4; p++) Ep[p] = Enp[p];
        rmc = rmn;
    }

    // epilogue: fold per-row scale into stored matrix (global max = 1)
    float rlmax = rowlog;
    #pragma unroll
    for (int off = 16; off; off >>= 1)
        rlmax = fmaxf(rlmax, __shfl_xor_sync(FULL, rlmax, off));
    float rsc = __expf(rowlog - rlmax);
    #pragma unroll
    for (int kk = 0; kk < 8; kk++)
        g_Rn[c][i*KK + h*8 + kk] = R[kk] * rsc;
    if (lane == 0) g_rc[c] = rmsum + rlmax;
}

// ---------------------------------------------------------------------------
// Phase 2: one 1024-thread block per batch. Scalar-scaled matrices:
// no per-row scale staging, no per-combine rlmax reductions.
// ---------------------------------------------------------------------------
__global__ void __launch_bounds__(TPB2) phase2_kernel(const float* __restrict__ start_logits) {
    extern __shared__ __align__(16) float sm2[];
    float* Rs   = sm2;                 // [NC][256]
    float* rc   = Rs + NC*256;         // [NC]
    float* Ss   = rc + NC;             // [NSUP][256]
    float* srcv = Ss + NSUP*256;       // [NSUP]
    float* qs   = srcv + NSUP;         // [NSUP][16]
    float* Cs   = qs + NSUP*16;        // [NSUP]

    int b = blockIdx.x;
    int tid = threadIdx.x;
    int w = tid >> 5, lane = tid & 31;
    int kk = lane & 15;

    // ---- staging ----
    {
        const float4* src = (const float4*)(&g_Rn[b*NC][0]);
        float4* dst = (float4*)Rs;
        for (int i = tid; i < NC*64; i += TPB2) dst[i] = __ldg(src + i);
        if (tid < NC) rc[tid] = __ldg(&g_rc[b*NC + tid]);
    }
    __syncthreads();

    int iRow = lane >> 1, h = lane & 1;

    // ---- super-combine: warp w (w < 16) -> super w ----
    if (w < NSUP) {
        int s = w;
        int c0 = s*SUPW;

        float acc[8];
        {
            const float4* p = (const float4*)(Rs + c0*256 + iRow*16 + h*8);
            float4 r0 = p[0], r1 = p[1];
            acc[0]=r0.x; acc[1]=r0.y; acc[2]=r0.z; acc[3]=r0.w;
            acc[4]=r1.x; acc[5]=r1.y; acc[6]=r1.z; acc[7]=r1.w;
        }
        float rlA = 0.f;

        for (int m = 1; m < SUPW; m++) {
            int cm = c0 + m;

            float rp[8];
            #pragma unroll
            for (int j = 0; j < 8; j++) rp[j] = __shfl_xor_sync(FULL, acc[j], 1);
            float ar[16];
            #pragma unroll
            for (int j = 0; j < 8; j++) {
                ar[j]   = h ? rp[j]  : acc[j];
                ar[j+8] = h ? acc[j] : rp[j];
            }

            float nw[8];
            #pragma unroll
            for (int kk2 = 0; kk2 < 8; kk2++) nw[kk2] = 0.f;
            #pragma unroll
            for (int j = 0; j < 16; j++) {
                const float4* pb = (const float4*)(Rs + cm*256 + j*16 + h*8);
                float4 b0 = pb[0], b1 = pb[1];
                float aj = ar[j];
                nw[0] = fmaf(aj, b0.x, nw[0]);
                nw[1] = fmaf(aj, b0.y, nw[1]);
                nw[2] = fmaf(aj, b0.z, nw[2]);
                nw[3] = fmaf(aj, b0.w, nw[3]);
                nw[4] = fmaf(aj, b1.x, nw[4]);
                nw[5] = fmaf(aj, b1.y, nw[5]);
                nw[6] = fmaf(aj, b1.z, nw[6]);
                nw[7] = fmaf(aj, b1.w, nw[7]);
            }
            // global renorm (full-warp max = max over all rows/cols)
            float mx = nw[0];
            #pragma unroll
            for (int kk2 = 1; kk2 < 8; kk2++) mx = fmaxf(mx, nw[kk2]);
            #pragma unroll
            for (int off = 16; off; off >>= 1)
                mx = fmaxf(mx, __shfl_xor_sync(FULL, mx, off));
            mx = fmaxf(mx, 1e-37f);
            float inv = __fdividef(1.f, mx);
            #pragma unroll
            for (int kk2 = 0; kk2 < 8; kk2++) acc[kk2] = nw[kk2] * inv;
            rlA += __logf(mx);
        }

        #pragma unroll
        for (int kk2 = 0; kk2 < 8; kk2++)
            Ss[s*256 + iRow*16 + h*8 + kk2] = acc[kk2];
        if (lane == 0) {
            float t = 0.f;
            #pragma unroll
            for (int m = 0; m < SUPW; m++) t += rc[c0 + m];
            srcv[s] = t + rlA;
        }
    }
    __syncthreads();

    // ---- warp 0: serial combine over 16 supers ----
    if (w == 0) {
        float sv = __ldg(start_logits + kk);
        float sm = sv;
        #pragma unroll
        for (int off = 8; off; off >>= 1) sm = fmaxf(sm, __shfl_xor_sync(FULL, sm, off));
        float se = __expf(sv - sm);
        #pragma unroll
        for (int off = 8; off; off >>= 1) se += __shfl_xor_sync(FULL, se, off);
        float lstart = sv - sm - __logf(se);

        float e0 = __ldg(&g_emp[(size_t)(b*SS)*KK + kk]);
        float t = lstart + e0;
        float m0 = t;
        #pragma unroll
        for (int off = 8; off; off >>= 1) m0 = fmaxf(m0, __shfl_xor_sync(FULL, m0, off));
        float q = __expf(t - m0);
        float C = __ldg(&g_rowmax[b*SS]) + m0;

        float Bc[16], Bn[16];
        #pragma unroll
        for (int i = 0; i < 16; i++) Bc[i] = Ss[i*16 + kk];

        for (int c = 0; c < NSUP; c++) {
            if (c > 0) {
                if (lane < 16) qs[c*16 + kk] = q;
                if (lane == 0) Cs[c] = C;
            }
            if (c + 1 < NSUP) {
                #pragma unroll
                for (int i = 0; i < 16; i++) Bn[i] = Ss[(c+1)*256 + i*16 + kk];
            }
            float s0 = 0.f, s1 = 0.f, s2 = 0.f, s3 = 0.f;
            #pragma unroll
            for (int j = 0; j < 16; j += 4) {
                s0 = fmaf(__shfl_sync(FULL, q, j + 0), Bc[j + 0], s0);
                s1 = fmaf(__shfl_sync(FULL, q, j + 1), Bc[j + 1], s1);
                s2 = fmaf(__shfl_sync(FULL, q, j + 2), Bc[j + 2], s2);
                s3 = fmaf(__shfl_sync(FULL, q, j + 3), Bc[j + 3], s3);
            }
            float v = (s0 + s1) + (s2 + s3);
            C += srcv[c];
            if ((c & 7) == 7) {
                float mv = v;
                #pragma unroll
                for (int off = 8; off; off >>= 1)
                    mv = fmaxf(mv, __shfl_xor_sync(FULL, mv, off));
                mv = fmaxf(mv, 1e-37f);
                q = __fdividef(v, mv);
                C += __logf(mv);
            } else {
                q = v;
            }
            #pragma unroll
            for (int i = 0; i < 16; i++) Bc[i] = Bn[i];
        }
    }
    __syncthreads();

    // ---- propagate: warp w (w < 16) -> super w ----
    if (w < NSUP) {
        int s = w;
        float q, C;
        if (s == 0) {
            float sv = __ldg(start_logits + kk);
            float sm = sv;
            #pragma unroll
            for (int off = 8; off; off >>= 1) sm = fmaxf(sm, __shfl_xor_sync(FULL, sm, off));
            float se = __expf(sv - sm);
            #pragma unroll
            for (int off = 8; off; off >>= 1) se += __shfl_xor_sync(FULL, se, off);
            float lstart = sv - sm - __logf(se);
            float e0 = __ldg(&g_emp[(size_t)(b*SS)*KK + kk]);
            float t = lstart + e0;
            float m0 = t;
            #pragma unroll
            for (int off = 8; off; off >>= 1) m0 = fmaxf(m0, __shfl_xor_sync(FULL, m0, off));
            q = __expf(t - m0);
            C = __ldg(&g_rowmax[b*SS]) + m0;
        } else {
            q = qs[s*16 + kk];
            C = Cs[s];
        }

        for (int m = 0; m < SUPW; m++) {
            int cl = s*SUPW + m;
            int gc = b*NC + cl;
            if (cl > 0) {
                if (lane < 16) g_qb[gc][kk] = q;
                if (lane == 0) g_Cb[gc] = C;
            }
            if (m + 1 < SUPW) {
                float s0 = 0.f, s1 = 0.f, s2 = 0.f, s3 = 0.f;
                #pragma unroll
                for (int j = 0; j < 16; j += 4) {
                    s0 = fmaf(__shfl_sync(FULL, q, j + 0), Rs[cl*256 + (j+0)*16 + kk], s0);
                    s1 = fmaf(__shfl_sync(FULL, q, j + 1), Rs[cl*256 + (j+1)*16 + kk], s1);
                    s2 = fmaf(__shfl_sync(FULL, q, j + 2), Rs[cl*256 + (j+2)*16 + kk], s2);
                    s3 = fmaf(__shfl_sync(FULL, q, j + 3), Rs[cl*256 + (j+3)*16 + kk], s3);
                }
                float v = (s0 + s1) + (s2 + s3);
                float mv = v;
                #pragma unroll
                for (int off = 8; off; off >>= 1)
                    mv = fmaxf(mv, __shfl_xor_sync(FULL, mv, off));
                mv = fmaxf(mv, 1e-37f);
                q = __fdividef(v, mv);
                C += rc[cl] + __logf(mv);
            }
        }
    }
}

// ---------------------------------------------------------------------------
// Phase 3: per-chunk vector recursion (R12 verbatim)
// ---------------------------------------------------------------------------
__global__ void __launch_bounds__(32) phase3_kernel(
    const float* __restrict__ start_logits, float* __restrict__ out)
{
    int c = blockIdx.x;
    int lane = threadIdx.x;
    int b = c / NC, cl = c % NC;
    int kk = lane & 15;

    float acol[KK];
    #pragma unroll
    for (int j = 0; j < KK; j++) acol[j] = __ldg(&g_A[j*KK + kk]);

    const float* pP = g_emp + (size_t)(b*SS + cl*CH)*KK;
    const float* prm = g_rowmax + b*SS + cl*CH;
    float* ob = out + (size_t)(b*SS + cl*CH)*KK;

    float bufE[CH], bufP[CH], rm[CH];
    #pragma unroll
    for (int u = 0; u < CH; u++) {
        bufP[u] = __ldg(pP + u*KK + kk);
        rm[u]   = __ldg(prm + u);
        bufE[u] = __expf(fmaxf(bufP[u], -80.f));
    }

    float q, C;
    if (cl == 0) {
        float sv = __ldg(start_logits + kk);
        float sm = sv;
        #pragma unroll
        for (int off = 8; off; off >>= 1) sm = fmaxf(sm, __shfl_xor_sync(FULL, sm, off));
        float se = __expf(sv - sm);
        #pragma unroll
        for (int off = 8; off; off >>= 1) se += __shfl_xor_sync(FULL, se, off);
        float lstart = sv - sm - __logf(se);

        float a0 = lstart + bufP[0] + rm[0];
        if (lane < 16) ob[kk] = a0;
        q = __expf(fmaxf(lstart + bufP[0], -80.f));
        C = rm[0];
    } else {
        q = __ldg(&g_qb[c][kk]);
        C = __ldg(&g_Cb[c]);
    }

    #pragma unroll
    for (int u = 0; u < CH; u++) {
        if (cl == 0 && u == 0) continue;
        float s0 = 0.f, s1 = 0.f, s2 = 0.f, s3 = 0.f;
        #pragma unroll
        for (int j = 0; j < KK; j += 4) {
            s0 = fmaf(__shfl_sync(FULL, q, j + 0), acol[j + 0], s0);
            s1 = fmaf(__shfl_sync(FULL, q, j + 1), acol[j + 1], s1);
            s2 = fmaf(__shfl_sync(FULL, q, j + 2), acol[j + 2], s2);
            s3 = fmaf(__shfl_sync(FULL, q, j + 3), acol[j + 3], s3);
        }
        float ssum = (s0 + s1) + (s2 + s3);
        ssum = fmaxf(ssum, 1e-37f);
        float ov = C + rm[u] + bufP[u] + __logf(ssum);
        if (lane < 16) ob[u*KK + kk] = ov;
        q = ssum * bufE[u];
        C += rm[u];
    }
}

// ---------------------------------------------------------------------------
extern "C" void kernel_launch(void* const* d_in, const int* in_sizes, int n_in,
                              void* d_out, int out_size) {
    const float* y   = (const float*)d_in[0];
    const float* z   = (const float*)d_in[1];
    const float* st  = (const float*)d_in[2];
    const float* tr  = (const float*)d_in[3];
    const float* mu  = (const float*)d_in[4];
    const float* lv  = (const float*)d_in[5];
    const float* wz  = (const float*)d_in[6];
    const float* ws  = (const float*)d_in[7];
    const float* bd  = (const float*)d_in[8];
    float* out = (float*)d_out;

    int em_smem = EM_TOTAL * sizeof(float);   // ~66.3 KB (dynamic)
    int p2_smem = (NC*256 + NC + NSUP*256 + NSUP + NSUP*16 + NSUP) * sizeof(float);
    cudaFuncSetAttribute(emissions_kernel,
                         cudaFuncAttributeMaxDynamicSharedMemorySize, em_smem);
    cudaFuncSetAttribute(phase2_kernel,
                         cudaFuncAttributeMaxDynamicSharedMemorySize, p2_smem);

    setup_kernel<<<KK, 32>>>(lv, ws, tr, mu);
    emissions_kernel<<<NS/SPB, TPB, em_smem>>>(y, z, wz, ws, bd);
    phase1_kernel<<<TOTCH, 32>>>();
    phase2_kernel<<<BB, TPB2, p2_smem>>>(st);
    phase3_kernel<<<TOTCH, 32>>>(st, out);
}